// round 13
// baseline (speedup 1.0000x reference)
#include <cuda_runtime.h>
#include <cuda_fp16.h>
#include <math.h>
#include <stdint.h>

// ---------------- problem constants ----------------
#define BT      8
#define SEQ     576
#define MTOT    (BT * SEQ)        // 4608
#define NLF     25
#define DIM     2048              // D
#define CTD     1024              // CT
#define HEADS   8
#define HDIM    128
#define ATT_SCALE 0.03125f
#define LN_EPSF   1e-5f
#define COS_EPSF  1e-8f

typedef unsigned long long ull;

// ---------------- device scratch ----------------
__device__ __half g_xn[(size_t)8 * MTOT * DIM];   // slots 0..6 LN'd layers, slot 7 raw layer 24
__device__ __half g_wh[(size_t)8 * DIM * CTD];    // slots 0..6 w_norm, slot 7 w_in (fp16)
__device__ __half g_woh[(size_t)CTD * CTD];       // w_out fp16
__device__ __half g_vh[(size_t)MTOT * 7 * CTD];   // vout slots 0..6, fp16
__device__ float  g_vin[(size_t)MTOT * CTD];      // vin fp32
__device__ __half g_fuse[(size_t)MTOT * CTD];
__device__ float  g_part[(size_t)8 * MTOT * 2];   // per-strip (dot, n1) partials
__device__ float  g_n2[MTOT];                     // teacher squared norms

// ---------------- helpers ----------------
__device__ __forceinline__ float warp_sum(float v) {
#pragma unroll
    for (int o = 16; o > 0; o >>= 1) v += __shfl_xor_sync(0xffffffffu, v, o);
    return v;
}
__device__ __forceinline__ void cp16(void* dst, const void* src) {
    uint32_t d = (uint32_t)__cvta_generic_to_shared(dst);
    asm volatile("cp.async.cg.shared.global [%0], [%1], 16;\n" :: "r"(d), "l"(src));
}
__device__ __forceinline__ uint2 f4_to_h4(float4 v) {
    __half2 lo = __floats2half2_rn(v.x, v.y);
    __half2 hi = __floats2half2_rn(v.z, v.w);
    uint2 r;
    r.x = *reinterpret_cast<uint32_t*>(&lo);
    r.y = *reinterpret_cast<uint32_t*>(&hi);
    return r;
}
// packed fp32x2 accumulate: acc += t (two independent fp32 adds)
__device__ __forceinline__ void addf2(float2& acc, float2 t) {
    ull* ap = reinterpret_cast<ull*>(&acc);
    ull tv = *reinterpret_cast<ull*>(&t);
    asm("add.rn.f32x2 %0, %0, %1;" : "+l"(*ap) : "l"(tv));
}

// ---------------- 1) fused prep: LN, weight conversion, teacher norms -------
// LN: 7 blocks per row (l=0..6); l==0 also writes the raw layer-24 copy (slot 7).
#define WN4 ((size_t)7 * DIM * CTD / 4)
#define WI4 ((size_t)DIM * CTD / 4)
#define WO4 ((size_t)CTD * CTD / 4)
#define LN_BLOCKS (MTOT * 7)
#define CW_TOTAL  (WN4 + WI4 + WO4)
#define CW_BLOCKS ((unsigned)((CW_TOTAL + 255) / 256))
#define PREP_BLOCKS (LN_BLOCKS + CW_BLOCKS + MTOT)

__global__ void __launch_bounds__(256) prep_kernel(
    const float* __restrict__ features,
    const float* __restrict__ ln_scale,
    const float* __restrict__ ln_bias,
    const float* __restrict__ wn,
    const float* __restrict__ wi,
    const float* __restrict__ wo,
    const float* __restrict__ teacher)
{
    if (blockIdx.x >= LN_BLOCKS + CW_BLOCKS) {
        // teacher norm^2 for one row
        int m = blockIdx.x - (LN_BLOCKS + CW_BLOCKS);
        int t = threadIdx.x;
        float4 y = reinterpret_cast<const float4*>(teacher + (size_t)m * CTD)[t];
        float n2 = y.x*y.x + y.y*y.y + y.z*y.z + y.w*y.w;
        __shared__ float s2[8];
        float w2 = warp_sum(n2);
        int w = t >> 5, lane = t & 31;
        if (lane == 0) s2[w] = w2;
        __syncthreads();
        if (t == 0) {
            float tot = 0.f;
#pragma unroll
            for (int i = 0; i < 8; i++) tot += s2[i];
            g_n2[m] = tot;
        }
        return;
    }
    if (blockIdx.x >= LN_BLOCKS) {
        size_t i = (size_t)(blockIdx.x - LN_BLOCKS) * 256 + threadIdx.x;
        if (i < WN4) {
            reinterpret_cast<uint2*>(g_wh)[i] =
                f4_to_h4(reinterpret_cast<const float4*>(wn)[i]);
        } else if (i < WN4 + WI4) {
            size_t j = i - WN4;
            reinterpret_cast<uint2*>(g_wh + (size_t)7 * DIM * CTD)[j] =
                f4_to_h4(reinterpret_cast<const float4*>(wi)[j]);
        } else if (i < WN4 + WI4 + WO4) {
            size_t j = i - WN4 - WI4;
            reinterpret_cast<uint2*>(g_woh)[j] =
                f4_to_h4(reinterpret_cast<const float4*>(wo)[j]);
        }
        return;
    }

    int l = blockIdx.x % 7;
    int m = blockIdx.x / 7;
    int layer = 24 - 4 * l;
    const float4* x = reinterpret_cast<const float4*>(
        features + ((size_t)m * NLF + layer) * DIM);
    int t = threadIdx.x;

    float4 a = x[t];
    float4 b = x[t + 256];
    uint2* o = reinterpret_cast<uint2*>(g_xn + ((size_t)l * MTOT + m) * DIM);

    if (l == 0) {
        // raw layer-24 copy to slot 7 (reuses the same loads)
        uint2* o7 = reinterpret_cast<uint2*>(g_xn + ((size_t)7 * MTOT + m) * DIM);
        o7[t] = f4_to_h4(a);
        o7[t + 256] = f4_to_h4(b);
    }

    float s  = a.x + a.y + a.z + a.w + b.x + b.y + b.z + b.w;
    float ss = a.x*a.x + a.y*a.y + a.z*a.z + a.w*a.w
             + b.x*b.x + b.y*b.y + b.z*b.z + b.w*b.w;

    __shared__ float shs[8], shss[8];
    float ws  = warp_sum(s);
    float wss = warp_sum(ss);
    int w = t >> 5, lane = t & 31;
    if (lane == 0) { shs[w] = ws; shss[w] = wss; }
    __syncthreads();
    float tot = 0.f, tot2 = 0.f;
#pragma unroll
    for (int i = 0; i < 8; i++) { tot += shs[i]; tot2 += shss[i]; }

    float mu  = tot * (1.0f / DIM);
    float var = tot2 * (1.0f / DIM) - mu * mu;
    float rs  = rsqrtf(var + LN_EPSF);

    const float4* sc = reinterpret_cast<const float4*>(ln_scale + (size_t)l * DIM);
    const float4* bi = reinterpret_cast<const float4*>(ln_bias  + (size_t)l * DIM);
    float4 s0 = sc[t],       b0 = bi[t];
    float4 s1 = sc[t + 256], b1 = bi[t + 256];
    float4 o0, o1;
    o0.x = (a.x - mu) * rs * s0.x + b0.x;
    o0.y = (a.y - mu) * rs * s0.y + b0.y;
    o0.z = (a.z - mu) * rs * s0.z + b0.z;
    o0.w = (a.w - mu) * rs * s0.w + b0.w;
    o1.x = (b.x - mu) * rs * s1.x + b1.x;
    o1.y = (b.y - mu) * rs * s1.y + b1.y;
    o1.z = (b.z - mu) * rs * s1.z + b1.z;
    o1.w = (b.w - mu) * rs * s1.w + b1.w;
    o[t] = f4_to_h4(o0);
    o[t + 256] = f4_to_h4(o1);
}

// ---------------- 2) HFMA2 GEMM: 128x128x32 tile, 256 thr, 8Mx8N/thread -----
// 2 CTAs/SM. A dup (v,v) half2 pairs in smem; B fp16 [K,N] natural via cp.async.
// half2 accumulators flushed to fp32 regs (f32x2 add) every 16 K-tiles (K=512).
// MODE 0: g_xn[z] @ g_wh[z] -> z<7: g_vh slot z (fp16); z==7: g_vin + b_in
// MODE 1: g_fuse @ g_woh + vin + b_out; fused cosine partials -> g_part
#define KT 32
template<int NKT, int MODE>
__global__ void __launch_bounds__(256, 2) gemm_h5(
    const float* __restrict__ bias,
    const float* __restrict__ teacher)
{
    __shared__ __align__(16) uint32_t As2[2][KT][128];  // dup half2 pairs, 32 KB
    __shared__ __align__(16) __half   Bs[2][KT][128];   // 16 KB

    int tid = threadIdx.x;
    int m0 = blockIdx.y * 128, n0 = blockIdx.x * 128;
    int z = (MODE == 0) ? blockIdx.z : 0;

    const __half* A;
    const __half* B;
    if (MODE == 0) {
        A = g_xn + (size_t)z * MTOT * DIM;
        B = g_wh + (size_t)z * DIM * CTD;
    } else {
        A = g_fuse;
        B = g_woh;
    }
    const int lda = (MODE == 0) ? DIM : CTD;

    // A loader: thread t -> row t>>1, k-cols (t&1)*16 .. +15 (two uint4)
    int arow = tid >> 1, acol = (tid & 1) * 16;
    const __half* ag = A + (size_t)(m0 + arow) * lda + acol;
    // B loader: thread t -> krow t>>3, cols (t&7)*16 .. +15 (two cp16)
    int brow = tid >> 3, bcol = (tid & 7) * 16;
    const __half* bg = B + (size_t)brow * CTD + n0 + bcol;

    // compute mapping: ty 0..15 (8 m-rows), tx 0..15 (8 n-cols)
    int ty = tid >> 4, tx = tid & 15;

    float2  accf[8][4];
    __half2 acch[8][4];
#pragma unroll
    for (int i = 0; i < 8; i++)
#pragma unroll
        for (int j = 0; j < 4; j++) {
            accf[i][j] = make_float2(0.f, 0.f);
            acch[i][j] = __half2half2(__ushort_as_half(0));
        }

    uint4 pa0, pa1;

    auto store_a = [&](int buf) {
        const __half2* h0 = reinterpret_cast<const __half2*>(&pa0);
        const __half2* h1 = reinterpret_cast<const __half2*>(&pa1);
#pragma unroll
        for (int jj = 0; jj < 4; jj++) {
            __half2 dlo = __half2half2(__low2half(h0[jj]));
            __half2 dhi = __half2half2(__high2half(h0[jj]));
            As2[buf][acol + 2 * jj][arow]     = *reinterpret_cast<uint32_t*>(&dlo);
            As2[buf][acol + 2 * jj + 1][arow] = *reinterpret_cast<uint32_t*>(&dhi);
        }
#pragma unroll
        for (int jj = 0; jj < 4; jj++) {
            __half2 dlo = __half2half2(__low2half(h1[jj]));
            __half2 dhi = __half2half2(__high2half(h1[jj]));
            As2[buf][acol + 8 + 2 * jj][arow]     = *reinterpret_cast<uint32_t*>(&dlo);
            As2[buf][acol + 8 + 2 * jj + 1][arow] = *reinterpret_cast<uint32_t*>(&dhi);
        }
    };

    // ---- prologue: tile 0 into buf 0 ----
    pa0 = *reinterpret_cast<const uint4*>(ag);
    pa1 = *reinterpret_cast<const uint4*>(ag + 8);
    cp16(&Bs[0][brow][bcol], bg);
    cp16(&Bs[0][brow][bcol + 8], bg + 8);
    asm volatile("cp.async.commit_group;\n" ::: "memory");
    store_a(0);

    for (int kt = 0; kt < NKT; kt++) {
        int buf = kt & 1;
        asm volatile("cp.async.wait_group 0;\n" ::: "memory");
        __syncthreads();

        if (kt + 1 < NKT) {
            pa0 = *reinterpret_cast<const uint4*>(ag + (kt + 1) * KT);
            pa1 = *reinterpret_cast<const uint4*>(ag + (kt + 1) * KT + 8);
            const __half* bn = bg + (size_t)(kt + 1) * KT * CTD;
            cp16(&Bs[buf ^ 1][brow][bcol], bn);
            cp16(&Bs[buf ^ 1][brow][bcol + 8], bn + 8);
            asm volatile("cp.async.commit_group;\n" ::: "memory");
        }

#pragma unroll
        for (int k = 0; k < KT; k++) {
            __half2 a2[8], b2[4];
            *reinterpret_cast<uint4*>(&a2[0]) =
                *reinterpret_cast<const uint4*>(&As2[buf][k][ty * 8]);
            *reinterpret_cast<uint4*>(&a2[4]) =
                *reinterpret_cast<const uint4*>(&As2[buf][k][ty * 8 + 4]);
            *reinterpret_cast<uint4*>(&b2[0]) =
                *reinterpret_cast<const uint4*>(&Bs[buf][k][tx * 8]);
#pragma unroll
            for (int i = 0; i < 8; i++)
#pragma unroll
                for (int j = 0; j < 4; j++)
                    acch[i][j] = __hfma2(a2[i], b2[j], acch[i][j]);
        }

        if (kt + 1 < NKT) store_a(buf ^ 1);

        if ((kt & 15) == 15 || kt == NKT - 1) {
#pragma unroll
            for (int i = 0; i < 8; i++)
#pragma unroll
                for (int j = 0; j < 4; j++) {
                    addf2(accf[i][j], __half22float2(acch[i][j]));
                    acch[i][j] = __half2half2(__ushort_as_half(0));
                }
        }
    }

    // ---- epilogue: 8 rows x 8 cols per thread ----
#pragma unroll
    for (int i = 0; i < 8; i++) {
        int m = m0 + ty * 8 + i;
        int n = n0 + tx * 8;
        float4 v0, v1;
        v0.x = accf[i][0].x; v0.y = accf[i][0].y;
        v0.z = accf[i][1].x; v0.w = accf[i][1].y;
        v1.x = accf[i][2].x; v1.y = accf[i][2].y;
        v1.z = accf[i][3].x; v1.w = accf[i][3].y;
        if (MODE == 0) {
            if (z < 7) {
                uint2 h0 = f4_to_h4(v0);
                uint2 h1 = f4_to_h4(v1);
                uint4 hv = make_uint4(h0.x, h0.y, h1.x, h1.y);
                *reinterpret_cast<uint4*>(
                    g_vh + (size_t)m * (7 * CTD) + (size_t)z * CTD + n) = hv;
            } else {
                float4 b0 = *reinterpret_cast<const float4*>(bias + n);
                float4 b1 = *reinterpret_cast<const float4*>(bias + n + 4);
                v0.x += b0.x; v0.y += b0.y; v0.z += b0.z; v0.w += b0.w;
                v1.x += b1.x; v1.y += b1.y; v1.z += b1.z; v1.w += b1.w;
                float* dst = g_vin + (size_t)m * CTD + n;
                *reinterpret_cast<float4*>(dst)     = v0;
                *reinterpret_cast<float4*>(dst + 4) = v1;
            }
        } else {
            float4 b0 = *reinterpret_cast<const float4*>(bias + n);
            float4 b1 = *reinterpret_cast<const float4*>(bias + n + 4);
            const float* vin = g_vin + (size_t)m * CTD + n;
            float4 i0 = *reinterpret_cast<const float4*>(vin);
            float4 i1 = *reinterpret_cast<const float4*>(vin + 4);
            v0.x += b0.x + i0.x; v0.y += b0.y + i0.y;
            v0.z += b0.z + i0.z; v0.w += b0.w + i0.w;
            v1.x += b1.x + i1.x; v1.y += b1.y + i1.y;
            v1.z += b1.z + i1.z; v1.w += b1.w + i1.w;
            // fused cosine partials for this 8-col strip of row m
            const float* tr = teacher + (size_t)m * CTD + n;
            float4 t0 = *reinterpret_cast<const float4*>(tr);
            float4 t1 = *reinterpret_cast<const float4*>(tr + 4);
            float pd = v0.x*t0.x + v0.y*t0.y + v0.z*t0.z + v0.w*t0.w
                     + v1.x*t1.x + v1.y*t1.y + v1.z*t1.z + v1.w*t1.w;
            float pn = v0.x*v0.x + v0.y*v0.y + v0.z*v0.z + v0.w*v0.w
                     + v1.x*v1.x + v1.y*v1.y + v1.z*v1.z + v1.w*v1.w;
#pragma unroll
            for (int o = 8; o > 0; o >>= 1) {
                pd += __shfl_xor_sync(0xffffffffu, pd, o);
                pn += __shfl_xor_sync(0xffffffffu, pn, o);
            }
            if (tx == 0) {
                float* dst = g_part + ((size_t)blockIdx.x * MTOT + m) * 2;
                dst[0] = pd;
                dst[1] = pn;
            }
        }
    }
}

// ---------------- 3) attention fuse: one warp per (m, head) ----------------
__global__ void __launch_bounds__(256) attn_kernel()
{
    int m = blockIdx.x;
    int h = threadIdx.x >> 5;
    int lane = threadIdx.x & 31;
    const __half* vrow = g_vh + (size_t)m * 7 * CTD + h * HDIM + lane * 4;

    float q[4], kv[6][4];
    {
        uint2 r = *reinterpret_cast<const uint2*>(vrow);
        float2 a = __half22float2(*reinterpret_cast<__half2*>(&r.x));
        float2 b = __half22float2(*reinterpret_cast<__half2*>(&r.y));
        q[0] = a.x * ATT_SCALE; q[1] = a.y * ATT_SCALE;
        q[2] = b.x * ATT_SCALE; q[3] = b.y * ATT_SCALE;
    }
#pragma unroll
    for (int l = 0; l < 6; l++) {
        uint2 r = *reinterpret_cast<const uint2*>(vrow + (size_t)(l + 1) * CTD);
        float2 a = __half22float2(*reinterpret_cast<__half2*>(&r.x));
        float2 b = __half22float2(*reinterpret_cast<__half2*>(&r.y));
        kv[l][0] = a.x; kv[l][1] = a.y; kv[l][2] = b.x; kv[l][3] = b.y;
    }

    float logit[6];
#pragma unroll
    for (int l = 0; l < 6; l++) {
        float p = q[0] * kv[l][0] + q[1] * kv[l][1]
                + q[2] * kv[l][2] + q[3] * kv[l][3];
        logit[l] = warp_sum(p);
    }

    float mx = -1e30f;
#pragma unroll
    for (int l = 0; l < 6; l++) mx = fmaxf(mx, logit[l]);
    float e[6], sum = 0.f;
#pragma unroll
    for (int l = 0; l < 6; l++) { e[l] = expf(logit[l] - mx); sum += e[l]; }
    float inv = 1.0f / sum;

    float f[4] = {0.f, 0.f, 0.f, 0.f};
#pragma unroll
    for (int l = 0; l < 6; l++) {
        float w = e[l] * inv;
#pragma unroll
        for (int d = 0; d < 4; d++) f[d] += w * kv[l][d];
    }

    __half2 lo = __floats2half2_rn(f[0], f[1]);
    __half2 hi = __floats2half2_rn(f[2], f[3]);
    uint2 outv;
    outv.x = *reinterpret_cast<uint32_t*>(&lo);
    outv.y = *reinterpret_cast<uint32_t*>(&hi);
    *reinterpret_cast<uint2*>(
        g_fuse + (size_t)m * CTD + h * HDIM + lane * 4) = outv;
}

// ---------------- 4) final: combine strips, cosine, deterministic mean ------
__global__ void __launch_bounds__(512) final_kernel(float* __restrict__ out)
{
    __shared__ float sh[512];
    int t = threadIdx.x;
    float s = 0.f;
    for (int m = t; m < MTOT; m += 512) {
        float dot = 0.f, n1 = 0.f;
#pragma unroll
        for (int st = 0; st < 8; st++) {
            const float* p = g_part + ((size_t)st * MTOT + m) * 2;
            dot += p[0];
            n1  += p[1];
        }
        float na = fmaxf(sqrtf(n1), COS_EPSF);
        float nb = fmaxf(sqrtf(g_n2[m]), COS_EPSF);
        s += dot / (na * nb);
    }
    sh[t] = s;
    __syncthreads();
    for (int o = 256; o > 0; o >>= 1) {
        if (t < o) sh[t] += sh[t + o];
        __syncthreads();
    }
    if (t == 0) out[0] = 1.0f - sh[0] / (float)MTOT;
}

// ---------------- launch ----------------
extern "C" void kernel_launch(void* const* d_in, const int* in_sizes, int n_in,
                              void* d_out, int out_size)
{
    const float* features = (const float*)d_in[0];
    const float* teacher  = (const float*)d_in[1];
    const float* ln_scale = (const float*)d_in[2];
    const float* ln_bias  = (const float*)d_in[3];
    const float* w_norm   = (const float*)d_in[4];
    const float* w_in     = (const float*)d_in[5];
    const float* b_in     = (const float*)d_in[6];
    const float* w_out    = (const float*)d_in[7];
    const float* b_out    = (const float*)d_in[8];
    float* out = (float*)d_out;

    prep_kernel<<<PREP_BLOCKS, 256>>>(
        features, ln_scale, ln_bias, w_norm, w_in, w_out, teacher);
    gemm_h5<DIM / KT, 0><<<dim3(CTD / 128, MTOT / 128, 8), 256>>>(b_in, nullptr);
    attn_kernel<<<MTOT, 256>>>();
    gemm_h5<CTD / KT, 1><<<dim3(CTD / 128, MTOT / 128, 1), 256>>>(b_out, teacher);
    final_kernel<<<1, 512>>>(out);
}

// round 14
// speedup vs baseline: 1.0119x; 1.0119x over previous
#include <cuda_runtime.h>
#include <cuda_fp16.h>
#include <math.h>
#include <stdint.h>

// ---------------- problem constants ----------------
#define BT      8
#define SEQ     576
#define MTOT    (BT * SEQ)        // 4608
#define NLF     25
#define DIM     2048              // D
#define CTD     1024              // CT
#define HEADS   8
#define HDIM    128
#define ATT_SCALE 0.03125f
#define LN_EPSF   1e-5f
#define COS_EPSF  1e-8f

// ---------------- device scratch ----------------
__device__ __half g_xn[(size_t)8 * MTOT * DIM];   // slots 0..6 LN'd layers, slot 7 raw layer 24
__device__ __half g_wh[(size_t)8 * DIM * CTD];    // slots 0..6 w_norm, slot 7 w_in (fp16)
__device__ __half g_woh[(size_t)CTD * CTD];       // w_out fp16
__device__ __half g_vh[(size_t)MTOT * 7 * CTD];   // vout slots 0..6, fp16
__device__ float  g_vin[(size_t)MTOT * CTD];      // vin fp32
__device__ __half g_fuse[(size_t)MTOT * CTD];
__device__ float  g_part[(size_t)8 * MTOT * 2];   // per-strip (dot, n1) partials
__device__ float  g_n2[MTOT];                     // teacher squared norms

// ---------------- helpers ----------------
__device__ __forceinline__ float warp_sum(float v) {
#pragma unroll
    for (int o = 16; o > 0; o >>= 1) v += __shfl_xor_sync(0xffffffffu, v, o);
    return v;
}
__device__ __forceinline__ void cp16(void* dst, const void* src) {
    uint32_t d = (uint32_t)__cvta_generic_to_shared(dst);
    asm volatile("cp.async.cg.shared.global [%0], [%1], 16;\n" :: "r"(d), "l"(src));
}
__device__ __forceinline__ uint2 f4_to_h4(float4 v) {
    __half2 lo = __floats2half2_rn(v.x, v.y);
    __half2 hi = __floats2half2_rn(v.z, v.w);
    uint2 r;
    r.x = *reinterpret_cast<uint32_t*>(&lo);
    r.y = *reinterpret_cast<uint32_t*>(&hi);
    return r;
}

// ---------------- 1) fused prep: LN, weight conversion, teacher norms -------
// LN: 7 blocks per row (l=0..6); l==0 also writes the raw layer-24 copy (slot 7).
#define WN4 ((size_t)7 * DIM * CTD / 4)
#define WI4 ((size_t)DIM * CTD / 4)
#define WO4 ((size_t)CTD * CTD / 4)
#define LN_BLOCKS (MTOT * 7)
#define CW_TOTAL  (WN4 + WI4 + WO4)
#define CW_BLOCKS ((unsigned)((CW_TOTAL + 255) / 256))
#define PREP_BLOCKS (LN_BLOCKS + CW_BLOCKS + MTOT)

__global__ void __launch_bounds__(256) prep_kernel(
    const float* __restrict__ features,
    const float* __restrict__ ln_scale,
    const float* __restrict__ ln_bias,
    const float* __restrict__ wn,
    const float* __restrict__ wi,
    const float* __restrict__ wo,
    const float* __restrict__ teacher)
{
    if (blockIdx.x >= LN_BLOCKS + CW_BLOCKS) {
        // teacher norm^2 for one row
        int m = blockIdx.x - (LN_BLOCKS + CW_BLOCKS);
        int t = threadIdx.x;
        float4 y = reinterpret_cast<const float4*>(teacher + (size_t)m * CTD)[t];
        float n2 = y.x*y.x + y.y*y.y + y.z*y.z + y.w*y.w;
        __shared__ float s2[8];
        float w2 = warp_sum(n2);
        int w = t >> 5, lane = t & 31;
        if (lane == 0) s2[w] = w2;
        __syncthreads();
        if (t == 0) {
            float tot = 0.f;
#pragma unroll
            for (int i = 0; i < 8; i++) tot += s2[i];
            g_n2[m] = tot;
        }
        return;
    }
    if (blockIdx.x >= LN_BLOCKS) {
        size_t i = (size_t)(blockIdx.x - LN_BLOCKS) * 256 + threadIdx.x;
        if (i < WN4) {
            reinterpret_cast<uint2*>(g_wh)[i] =
                f4_to_h4(reinterpret_cast<const float4*>(wn)[i]);
        } else if (i < WN4 + WI4) {
            size_t j = i - WN4;
            reinterpret_cast<uint2*>(g_wh + (size_t)7 * DIM * CTD)[j] =
                f4_to_h4(reinterpret_cast<const float4*>(wi)[j]);
        } else if (i < WN4 + WI4 + WO4) {
            size_t j = i - WN4 - WI4;
            reinterpret_cast<uint2*>(g_woh)[j] =
                f4_to_h4(reinterpret_cast<const float4*>(wo)[j]);
        }
        return;
    }

    int l = blockIdx.x % 7;
    int m = blockIdx.x / 7;
    int layer = 24 - 4 * l;
    const float4* x = reinterpret_cast<const float4*>(
        features + ((size_t)m * NLF + layer) * DIM);
    int t = threadIdx.x;

    float4 a = x[t];
    float4 b = x[t + 256];
    uint2* o = reinterpret_cast<uint2*>(g_xn + ((size_t)l * MTOT + m) * DIM);

    if (l == 0) {
        // raw layer-24 copy to slot 7 (reuses the same loads)
        uint2* o7 = reinterpret_cast<uint2*>(g_xn + ((size_t)7 * MTOT + m) * DIM);
        o7[t] = f4_to_h4(a);
        o7[t + 256] = f4_to_h4(b);
    }

    float s  = a.x + a.y + a.z + a.w + b.x + b.y + b.z + b.w;
    float ss = a.x*a.x + a.y*a.y + a.z*a.z + a.w*a.w
             + b.x*b.x + b.y*b.y + b.z*b.z + b.w*b.w;

    __shared__ float shs[8], shss[8];
    float ws  = warp_sum(s);
    float wss = warp_sum(ss);
    int w = t >> 5, lane = t & 31;
    if (lane == 0) { shs[w] = ws; shss[w] = wss; }
    __syncthreads();
    float tot = 0.f, tot2 = 0.f;
#pragma unroll
    for (int i = 0; i < 8; i++) { tot += shs[i]; tot2 += shss[i]; }

    float mu  = tot * (1.0f / DIM);
    float var = tot2 * (1.0f / DIM) - mu * mu;
    float rs  = rsqrtf(var + LN_EPSF);

    const float4* sc = reinterpret_cast<const float4*>(ln_scale + (size_t)l * DIM);
    const float4* bi = reinterpret_cast<const float4*>(ln_bias  + (size_t)l * DIM);
    float4 s0 = sc[t],       b0 = bi[t];
    float4 s1 = sc[t + 256], b1 = bi[t + 256];
    float4 o0, o1;
    o0.x = (a.x - mu) * rs * s0.x + b0.x;
    o0.y = (a.y - mu) * rs * s0.y + b0.y;
    o0.z = (a.z - mu) * rs * s0.z + b0.z;
    o0.w = (a.w - mu) * rs * s0.w + b0.w;
    o1.x = (b.x - mu) * rs * s1.x + b1.x;
    o1.y = (b.y - mu) * rs * s1.y + b1.y;
    o1.z = (b.z - mu) * rs * s1.z + b1.z;
    o1.w = (b.w - mu) * rs * s1.w + b1.w;
    o[t] = f4_to_h4(o0);
    o[t + 256] = f4_to_h4(o1);
}

// ---------------- 2) HFMA2 GEMM (R12 config): 128x128x32, 256 thr -----------
// 2 CTAs/SM. A dup (v,v) half2 pairs in smem; B fp16 [K,N] natural via cp.async.
// half2 accumulators flushed to fp32 regs every 8 K-tiles (K=256 window).
// MODE 0: g_xn[z] @ g_wh[z] -> z<7: g_vh slot z (fp16); z==7: g_vin + b_in
// MODE 1: g_fuse @ g_woh + vin + b_out; fused cosine partials -> g_part
#define KT 32
template<int NKT, int MODE>
__global__ void __launch_bounds__(256, 2) gemm_h5(
    const float* __restrict__ bias,
    const float* __restrict__ teacher)
{
    __shared__ __align__(16) uint32_t As2[2][KT][128];  // dup half2 pairs, 32 KB
    __shared__ __align__(16) __half   Bs[2][KT][128];   // 16 KB

    int tid = threadIdx.x;
    int m0 = blockIdx.y * 128, n0 = blockIdx.x * 128;
    int z = (MODE == 0) ? blockIdx.z : 0;

    const __half* A;
    const __half* B;
    if (MODE == 0) {
        A = g_xn + (size_t)z * MTOT * DIM;
        B = g_wh + (size_t)z * DIM * CTD;
    } else {
        A = g_fuse;
        B = g_woh;
    }
    const int lda = (MODE == 0) ? DIM : CTD;

    // A loader: thread t -> row t>>1, k-cols (t&1)*16 .. +15 (two uint4)
    int arow = tid >> 1, acol = (tid & 1) * 16;
    const __half* ag = A + (size_t)(m0 + arow) * lda + acol;
    // B loader: thread t -> krow t>>3, cols (t&7)*16 .. +15 (two cp16)
    int brow = tid >> 3, bcol = (tid & 7) * 16;
    const __half* bg = B + (size_t)brow * CTD + n0 + bcol;

    // compute mapping: ty 0..15 (8 m-rows), tx 0..15 (8 n-cols)
    int ty = tid >> 4, tx = tid & 15;

    float2  accf[8][4];
    __half2 acch[8][4];
#pragma unroll
    for (int i = 0; i < 8; i++)
#pragma unroll
        for (int j = 0; j < 4; j++) {
            accf[i][j] = make_float2(0.f, 0.f);
            acch[i][j] = __half2half2(__ushort_as_half(0));
        }

    uint4 pa0, pa1;

    auto store_a = [&](int buf) {
        const __half2* h0 = reinterpret_cast<const __half2*>(&pa0);
        const __half2* h1 = reinterpret_cast<const __half2*>(&pa1);
#pragma unroll
        for (int jj = 0; jj < 4; jj++) {
            __half2 dlo = __half2half2(__low2half(h0[jj]));
            __half2 dhi = __half2half2(__high2half(h0[jj]));
            As2[buf][acol + 2 * jj][arow]     = *reinterpret_cast<uint32_t*>(&dlo);
            As2[buf][acol + 2 * jj + 1][arow] = *reinterpret_cast<uint32_t*>(&dhi);
        }
#pragma unroll
        for (int jj = 0; jj < 4; jj++) {
            __half2 dlo = __half2half2(__low2half(h1[jj]));
            __half2 dhi = __half2half2(__high2half(h1[jj]));
            As2[buf][acol + 8 + 2 * jj][arow]     = *reinterpret_cast<uint32_t*>(&dlo);
            As2[buf][acol + 8 + 2 * jj + 1][arow] = *reinterpret_cast<uint32_t*>(&dhi);
        }
    };

    // ---- prologue: tile 0 into buf 0 ----
    pa0 = *reinterpret_cast<const uint4*>(ag);
    pa1 = *reinterpret_cast<const uint4*>(ag + 8);
    cp16(&Bs[0][brow][bcol], bg);
    cp16(&Bs[0][brow][bcol + 8], bg + 8);
    asm volatile("cp.async.commit_group;\n" ::: "memory");
    store_a(0);

    for (int kt = 0; kt < NKT; kt++) {
        int buf = kt & 1;
        asm volatile("cp.async.wait_group 0;\n" ::: "memory");
        __syncthreads();

        if (kt + 1 < NKT) {
            pa0 = *reinterpret_cast<const uint4*>(ag + (kt + 1) * KT);
            pa1 = *reinterpret_cast<const uint4*>(ag + (kt + 1) * KT + 8);
            const __half* bn = bg + (size_t)(kt + 1) * KT * CTD;
            cp16(&Bs[buf ^ 1][brow][bcol], bn);
            cp16(&Bs[buf ^ 1][brow][bcol + 8], bn + 8);
            asm volatile("cp.async.commit_group;\n" ::: "memory");
        }

#pragma unroll
        for (int k = 0; k < KT; k++) {
            __half2 a2[8], b2[4];
            *reinterpret_cast<uint4*>(&a2[0]) =
                *reinterpret_cast<const uint4*>(&As2[buf][k][ty * 8]);
            *reinterpret_cast<uint4*>(&a2[4]) =
                *reinterpret_cast<const uint4*>(&As2[buf][k][ty * 8 + 4]);
            *reinterpret_cast<uint4*>(&b2[0]) =
                *reinterpret_cast<const uint4*>(&Bs[buf][k][tx * 8]);
#pragma unroll
            for (int i = 0; i < 8; i++)
#pragma unroll
                for (int j = 0; j < 4; j++)
                    acch[i][j] = __hfma2(a2[i], b2[j], acch[i][j]);
        }

        if (kt + 1 < NKT) store_a(buf ^ 1);

        if ((kt & 7) == 7 || kt == NKT - 1) {
#pragma unroll
            for (int i = 0; i < 8; i++)
#pragma unroll
                for (int j = 0; j < 4; j++) {
                    float2 t = __half22float2(acch[i][j]);
                    accf[i][j].x += t.x;
                    accf[i][j].y += t.y;
                    acch[i][j] = __half2half2(__ushort_as_half(0));
                }
        }
    }

    // ---- epilogue: 8 rows x 8 cols per thread ----
#pragma unroll
    for (int i = 0; i < 8; i++) {
        int m = m0 + ty * 8 + i;
        int n = n0 + tx * 8;
        float4 v0, v1;
        v0.x = accf[i][0].x; v0.y = accf[i][0].y;
        v0.z = accf[i][1].x; v0.w = accf[i][1].y;
        v1.x = accf[i][2].x; v1.y = accf[i][2].y;
        v1.z = accf[i][3].x; v1.w = accf[i][3].y;
        if (MODE == 0) {
            if (z < 7) {
                uint2 h0 = f4_to_h4(v0);
                uint2 h1 = f4_to_h4(v1);
                uint4 hv = make_uint4(h0.x, h0.y, h1.x, h1.y);
                *reinterpret_cast<uint4*>(
                    g_vh + (size_t)m * (7 * CTD) + (size_t)z * CTD + n) = hv;
            } else {
                float4 b0 = *reinterpret_cast<const float4*>(bias + n);
                float4 b1 = *reinterpret_cast<const float4*>(bias + n + 4);
                v0.x += b0.x; v0.y += b0.y; v0.z += b0.z; v0.w += b0.w;
                v1.x += b1.x; v1.y += b1.y; v1.z += b1.z; v1.w += b1.w;
                float* dst = g_vin + (size_t)m * CTD + n;
                *reinterpret_cast<float4*>(dst)     = v0;
                *reinterpret_cast<float4*>(dst + 4) = v1;
            }
        } else {
            float4 b0 = *reinterpret_cast<const float4*>(bias + n);
            float4 b1 = *reinterpret_cast<const float4*>(bias + n + 4);
            const float* vin = g_vin + (size_t)m * CTD + n;
            float4 i0 = *reinterpret_cast<const float4*>(vin);
            float4 i1 = *reinterpret_cast<const float4*>(vin + 4);
            v0.x += b0.x + i0.x; v0.y += b0.y + i0.y;
            v0.z += b0.z + i0.z; v0.w += b0.w + i0.w;
            v1.x += b1.x + i1.x; v1.y += b1.y + i1.y;
            v1.z += b1.z + i1.z; v1.w += b1.w + i1.w;
            // fused cosine partials for this 8-col strip of row m
            const float* tr = teacher + (size_t)m * CTD + n;
            float4 t0 = *reinterpret_cast<const float4*>(tr);
            float4 t1 = *reinterpret_cast<const float4*>(tr + 4);
            float pd = v0.x*t0.x + v0.y*t0.y + v0.z*t0.z + v0.w*t0.w
                     + v1.x*t1.x + v1.y*t1.y + v1.z*t1.z + v1.w*t1.w;
            float pn = v0.x*v0.x + v0.y*v0.y + v0.z*v0.z + v0.w*v0.w
                     + v1.x*v1.x + v1.y*v1.y + v1.z*v1.z + v1.w*v1.w;
#pragma unroll
            for (int o = 8; o > 0; o >>= 1) {
                pd += __shfl_xor_sync(0xffffffffu, pd, o);
                pn += __shfl_xor_sync(0xffffffffu, pn, o);
            }
            if (tx == 0) {
                float* dst = g_part + ((size_t)blockIdx.x * MTOT + m) * 2;
                dst[0] = pd;
                dst[1] = pn;
            }
        }
    }
}

// ---------------- 3) attention fuse: one warp per (m, head) ----------------
__global__ void __launch_bounds__(256) attn_kernel()
{
    int m = blockIdx.x;
    int h = threadIdx.x >> 5;
    int lane = threadIdx.x & 31;
    const __half* vrow = g_vh + (size_t)m * 7 * CTD + h * HDIM + lane * 4;

    float q[4], kv[6][4];
    {
        uint2 r = *reinterpret_cast<const uint2*>(vrow);
        float2 a = __half22float2(*reinterpret_cast<__half2*>(&r.x));
        float2 b = __half22float2(*reinterpret_cast<__half2*>(&r.y));
        q[0] = a.x * ATT_SCALE; q[1] = a.y * ATT_SCALE;
        q[2] = b.x * ATT_SCALE; q[3] = b.y * ATT_SCALE;
    }
#pragma unroll
    for (int l = 0; l < 6; l++) {
        uint2 r = *reinterpret_cast<const uint2*>(vrow + (size_t)(l + 1) * CTD);
        float2 a = __half22float2(*reinterpret_cast<__half2*>(&r.x));
        float2 b = __half22float2(*reinterpret_cast<__half2*>(&r.y));
        kv[l][0] = a.x; kv[l][1] = a.y; kv[l][2] = b.x; kv[l][3] = b.y;
    }

    float logit[6];
#pragma unroll
    for (int l = 0; l < 6; l++) {
        float p = q[0] * kv[l][0] + q[1] * kv[l][1]
                + q[2] * kv[l][2] + q[3] * kv[l][3];
        logit[l] = warp_sum(p);
    }

    float mx = -1e30f;
#pragma unroll
    for (int l = 0; l < 6; l++) mx = fmaxf(mx, logit[l]);
    float e[6], sum = 0.f;
#pragma unroll
    for (int l = 0; l < 6; l++) { e[l] = expf(logit[l] - mx); sum += e[l]; }
    float inv = 1.0f / sum;

    float f[4] = {0.f, 0.f, 0.f, 0.f};
#pragma unroll
    for (int l = 0; l < 6; l++) {
        float w = e[l] * inv;
#pragma unroll
        for (int d = 0; d < 4; d++) f[d] += w * kv[l][d];
    }

    __half2 lo = __floats2half2_rn(f[0], f[1]);
    __half2 hi = __floats2half2_rn(f[2], f[3]);
    uint2 outv;
    outv.x = *reinterpret_cast<uint32_t*>(&lo);
    outv.y = *reinterpret_cast<uint32_t*>(&hi);
    *reinterpret_cast<uint2*>(
        g_fuse + (size_t)m * CTD + h * HDIM + lane * 4) = outv;
}

// ---------------- 4) final: combine strips, cosine, deterministic mean ------
__global__ void __launch_bounds__(512) final_kernel(float* __restrict__ out)
{
    __shared__ float sh[512];
    int t = threadIdx.x;
    float s = 0.f;
    for (int m = t; m < MTOT; m += 512) {
        float dot = 0.f, n1 = 0.f;
#pragma unroll
        for (int st = 0; st < 8; st++) {
            const float* p = g_part + ((size_t)st * MTOT + m) * 2;
            dot += p[0];
            n1  += p[1];
        }
        float na = fmaxf(sqrtf(n1), COS_EPSF);
        float nb = fmaxf(sqrtf(g_n2[m]), COS_EPSF);
        s += dot / (na * nb);
    }
    sh[t] = s;
    __syncthreads();
    for (int o = 256; o > 0; o >>= 1) {
        if (t < o) sh[t] += sh[t + o];
        __syncthreads();
    }
    if (t == 0) out[0] = 1.0f - sh[0] / (float)MTOT;
}

// ---------------- launch ----------------
extern "C" void kernel_launch(void* const* d_in, const int* in_sizes, int n_in,
                              void* d_out, int out_size)
{
    const float* features = (const float*)d_in[0];
    const float* teacher  = (const float*)d_in[1];
    const float* ln_scale = (const float*)d_in[2];
    const float* ln_bias  = (const float*)d_in[3];
    const float* w_norm   = (const float*)d_in[4];
    const float* w_in     = (const float*)d_in[5];
    const float* b_in     = (const float*)d_in[6];
    const float* w_out    = (const float*)d_in[7];
    const float* b_out    = (const float*)d_in[8];
    float* out = (float*)d_out;

    prep_kernel<<<PREP_BLOCKS, 256>>>(
        features, ln_scale, ln_bias, w_norm, w_in, w_out, teacher);
    gemm_h5<DIM / KT, 0><<<dim3(CTD / 128, MTOT / 128, 8), 256>>>(b_in, nullptr);
    attn_kernel<<<MTOT, 256>>>();
    gemm_h5<CTD / KT, 1><<<dim3(CTD / 128, MTOT / 128, 1), 256>>>(b_out, teacher);
    final_kernel<<<1, 512>>>(out);
}

// round 15
// speedup vs baseline: 1.0121x; 1.0002x over previous
#include <cuda_runtime.h>
#include <cuda_fp16.h>
#include <math.h>
#include <stdint.h>

// ---------------- problem constants ----------------
#define BT      8
#define SEQ     576
#define MTOT    (BT * SEQ)        // 4608
#define NLF     25
#define DIM     2048              // D
#define CTD     1024              // CT
#define HEADS   8
#define HDIM    128
#define ATT_SCALE 0.03125f
#define LN_EPSF   1e-5f
#define COS_EPSF  1e-8f

// ---------------- device scratch ----------------
__device__ __half g_xn[(size_t)8 * MTOT * DIM];   // slots 0..6 LN'd layers, slot 7 raw layer 24
__device__ __half g_wh[(size_t)8 * DIM * CTD];    // slots 0..6 w_norm, slot 7 w_in (fp16)
__device__ __half g_woh[(size_t)CTD * CTD];       // w_out fp16
__device__ __half g_vh[(size_t)MTOT * 7 * CTD];   // vout slots 0..6, fp16
__device__ float  g_vin[(size_t)MTOT * CTD];      // vin fp32
__device__ __half g_fuse[(size_t)MTOT * CTD];
__device__ float  g_part[(size_t)8 * MTOT * 2];   // per-strip (dot, n1) partials
__device__ float  g_n2[MTOT];                     // teacher squared norms

// ---------------- helpers ----------------
__device__ __forceinline__ float warp_sum(float v) {
#pragma unroll
    for (int o = 16; o > 0; o >>= 1) v += __shfl_xor_sync(0xffffffffu, v, o);
    return v;
}
__device__ __forceinline__ void cp16(void* dst, const void* src) {
    uint32_t d = (uint32_t)__cvta_generic_to_shared(dst);
    asm volatile("cp.async.cg.shared.global [%0], [%1], 16;\n" :: "r"(d), "l"(src));
}
__device__ __forceinline__ uint2 f4_to_h4(float4 v) {
    __half2 lo = __floats2half2_rn(v.x, v.y);
    __half2 hi = __floats2half2_rn(v.z, v.w);
    uint2 r;
    r.x = *reinterpret_cast<uint32_t*>(&lo);
    r.y = *reinterpret_cast<uint32_t*>(&hi);
    return r;
}

// ---------------- 1) fused prep: LN, weight conversion, teacher norms -------
#define WN4 ((size_t)7 * DIM * CTD / 4)
#define WI4 ((size_t)DIM * CTD / 4)
#define WO4 ((size_t)CTD * CTD / 4)
#define LN_BLOCKS (MTOT * 7)
#define CW_TOTAL  (WN4 + WI4 + WO4)
#define CW_BLOCKS ((unsigned)((CW_TOTAL + 255) / 256))
#define PREP_BLOCKS (LN_BLOCKS + CW_BLOCKS + MTOT)

__global__ void __launch_bounds__(256) prep_kernel(
    const float* __restrict__ features,
    const float* __restrict__ ln_scale,
    const float* __restrict__ ln_bias,
    const float* __restrict__ wn,
    const float* __restrict__ wi,
    const float* __restrict__ wo,
    const float* __restrict__ teacher)
{
    if (blockIdx.x >= LN_BLOCKS + CW_BLOCKS) {
        int m = blockIdx.x - (LN_BLOCKS + CW_BLOCKS);
        int t = threadIdx.x;
        float4 y = reinterpret_cast<const float4*>(teacher + (size_t)m * CTD)[t];
        float n2 = y.x*y.x + y.y*y.y + y.z*y.z + y.w*y.w;
        __shared__ float s2[8];
        float w2 = warp_sum(n2);
        int w = t >> 5, lane = t & 31;
        if (lane == 0) s2[w] = w2;
        __syncthreads();
        if (t == 0) {
            float tot = 0.f;
#pragma unroll
            for (int i = 0; i < 8; i++) tot += s2[i];
            g_n2[m] = tot;
        }
        return;
    }
    if (blockIdx.x >= LN_BLOCKS) {
        size_t i = (size_t)(blockIdx.x - LN_BLOCKS) * 256 + threadIdx.x;
        if (i < WN4) {
            reinterpret_cast<uint2*>(g_wh)[i] =
                f4_to_h4(reinterpret_cast<const float4*>(wn)[i]);
        } else if (i < WN4 + WI4) {
            size_t j = i - WN4;
            reinterpret_cast<uint2*>(g_wh + (size_t)7 * DIM * CTD)[j] =
                f4_to_h4(reinterpret_cast<const float4*>(wi)[j]);
        } else if (i < WN4 + WI4 + WO4) {
            size_t j = i - WN4 - WI4;
            reinterpret_cast<uint2*>(g_woh)[j] =
                f4_to_h4(reinterpret_cast<const float4*>(wo)[j]);
        }
        return;
    }

    int l = blockIdx.x % 7;
    int m = blockIdx.x / 7;
    int layer = 24 - 4 * l;
    const float4* x = reinterpret_cast<const float4*>(
        features + ((size_t)m * NLF + layer) * DIM);
    int t = threadIdx.x;

    float4 a = x[t];
    float4 b = x[t + 256];
    uint2* o = reinterpret_cast<uint2*>(g_xn + ((size_t)l * MTOT + m) * DIM);

    if (l == 0) {
        uint2* o7 = reinterpret_cast<uint2*>(g_xn + ((size_t)7 * MTOT + m) * DIM);
        o7[t] = f4_to_h4(a);
        o7[t + 256] = f4_to_h4(b);
    }

    float s  = a.x + a.y + a.z + a.w + b.x + b.y + b.z + b.w;
    float ss = a.x*a.x + a.y*a.y + a.z*a.z + a.w*a.w
             + b.x*b.x + b.y*b.y + b.z*b.z + b.w*b.w;

    __shared__ float shs[8], shss[8];
    float ws  = warp_sum(s);
    float wss = warp_sum(ss);
    int w = t >> 5, lane = t & 31;
    if (lane == 0) { shs[w] = ws; shss[w] = wss; }
    __syncthreads();
    float tot = 0.f, tot2 = 0.f;
#pragma unroll
    for (int i = 0; i < 8; i++) { tot += shs[i]; tot2 += shss[i]; }

    float mu  = tot * (1.0f / DIM);
    float var = tot2 * (1.0f / DIM) - mu * mu;
    float rs  = rsqrtf(var + LN_EPSF);

    const float4* sc = reinterpret_cast<const float4*>(ln_scale + (size_t)l * DIM);
    const float4* bi = reinterpret_cast<const float4*>(ln_bias  + (size_t)l * DIM);
    float4 s0 = sc[t],       b0 = bi[t];
    float4 s1 = sc[t + 256], b1 = bi[t + 256];
    float4 o0, o1;
    o0.x = (a.x - mu) * rs * s0.x + b0.x;
    o0.y = (a.y - mu) * rs * s0.y + b0.y;
    o0.z = (a.z - mu) * rs * s0.z + b0.z;
    o0.w = (a.w - mu) * rs * s0.w + b0.w;
    o1.x = (b.x - mu) * rs * s1.x + b1.x;
    o1.y = (b.y - mu) * rs * s1.y + b1.y;
    o1.z = (b.z - mu) * rs * s1.z + b1.z;
    o1.w = (b.w - mu) * rs * s1.w + b1.w;
    o[t] = f4_to_h4(o0);
    o[t + 256] = f4_to_h4(o1);
}

// ---------------- 2a) HFMA2 GEMM (R14/R12 config) — gemm1 ------------------
#define KT 32
template<int NKT>
__global__ void __launch_bounds__(256, 2) gemm_h5(
    const float* __restrict__ bias)
{
    __shared__ __align__(16) uint32_t As2[2][KT][128];  // dup half2 pairs, 32 KB
    __shared__ __align__(16) __half   Bs[2][KT][128];   // 16 KB

    int tid = threadIdx.x;
    int m0 = blockIdx.y * 128, n0 = blockIdx.x * 128;
    int z = blockIdx.z;

    const __half* A = g_xn + (size_t)z * MTOT * DIM;
    const __half* B = g_wh + (size_t)z * DIM * CTD;
    const int lda = DIM;

    int arow = tid >> 1, acol = (tid & 1) * 16;
    const __half* ag = A + (size_t)(m0 + arow) * lda + acol;
    int brow = tid >> 3, bcol = (tid & 7) * 16;
    const __half* bg = B + (size_t)brow * CTD + n0 + bcol;

    int ty = tid >> 4, tx = tid & 15;

    float2  accf[8][4];
    __half2 acch[8][4];
#pragma unroll
    for (int i = 0; i < 8; i++)
#pragma unroll
        for (int j = 0; j < 4; j++) {
            accf[i][j] = make_float2(0.f, 0.f);
            acch[i][j] = __half2half2(__ushort_as_half(0));
        }

    uint4 pa0, pa1;

    auto store_a = [&](int buf) {
        const __half2* h0 = reinterpret_cast<const __half2*>(&pa0);
        const __half2* h1 = reinterpret_cast<const __half2*>(&pa1);
#pragma unroll
        for (int jj = 0; jj < 4; jj++) {
            __half2 dlo = __half2half2(__low2half(h0[jj]));
            __half2 dhi = __half2half2(__high2half(h0[jj]));
            As2[buf][acol + 2 * jj][arow]     = *reinterpret_cast<uint32_t*>(&dlo);
            As2[buf][acol + 2 * jj + 1][arow] = *reinterpret_cast<uint32_t*>(&dhi);
        }
#pragma unroll
        for (int jj = 0; jj < 4; jj++) {
            __half2 dlo = __half2half2(__low2half(h1[jj]));
            __half2 dhi = __half2half2(__high2half(h1[jj]));
            As2[buf][acol + 8 + 2 * jj][arow]     = *reinterpret_cast<uint32_t*>(&dlo);
            As2[buf][acol + 8 + 2 * jj + 1][arow] = *reinterpret_cast<uint32_t*>(&dhi);
        }
    };

    pa0 = *reinterpret_cast<const uint4*>(ag);
    pa1 = *reinterpret_cast<const uint4*>(ag + 8);
    cp16(&Bs[0][brow][bcol], bg);
    cp16(&Bs[0][brow][bcol + 8], bg + 8);
    asm volatile("cp.async.commit_group;\n" ::: "memory");
    store_a(0);

    for (int kt = 0; kt < NKT; kt++) {
        int buf = kt & 1;
        asm volatile("cp.async.wait_group 0;\n" ::: "memory");
        __syncthreads();

        if (kt + 1 < NKT) {
            pa0 = *reinterpret_cast<const uint4*>(ag + (kt + 1) * KT);
            pa1 = *reinterpret_cast<const uint4*>(ag + (kt + 1) * KT + 8);
            const __half* bn = bg + (size_t)(kt + 1) * KT * CTD;
            cp16(&Bs[buf ^ 1][brow][bcol], bn);
            cp16(&Bs[buf ^ 1][brow][bcol + 8], bn + 8);
            asm volatile("cp.async.commit_group;\n" ::: "memory");
        }

#pragma unroll
        for (int k = 0; k < KT; k++) {
            __half2 a2[8], b2[4];
            *reinterpret_cast<uint4*>(&a2[0]) =
                *reinterpret_cast<const uint4*>(&As2[buf][k][ty * 8]);
            *reinterpret_cast<uint4*>(&a2[4]) =
                *reinterpret_cast<const uint4*>(&As2[buf][k][ty * 8 + 4]);
            *reinterpret_cast<uint4*>(&b2[0]) =
                *reinterpret_cast<const uint4*>(&Bs[buf][k][tx * 8]);
#pragma unroll
            for (int i = 0; i < 8; i++)
#pragma unroll
                for (int j = 0; j < 4; j++)
                    acch[i][j] = __hfma2(a2[i], b2[j], acch[i][j]);
        }

        if (kt + 1 < NKT) store_a(buf ^ 1);

        if ((kt & 7) == 7 || kt == NKT - 1) {
#pragma unroll
            for (int i = 0; i < 8; i++)
#pragma unroll
                for (int j = 0; j < 4; j++) {
                    float2 t = __half22float2(acch[i][j]);
                    accf[i][j].x += t.x;
                    accf[i][j].y += t.y;
                    acch[i][j] = __half2half2(__ushort_as_half(0));
                }
        }
    }

#pragma unroll
    for (int i = 0; i < 8; i++) {
        int m = m0 + ty * 8 + i;
        int n = n0 + tx * 8;
        float4 v0, v1;
        v0.x = accf[i][0].x; v0.y = accf[i][0].y;
        v0.z = accf[i][1].x; v0.w = accf[i][1].y;
        v1.x = accf[i][2].x; v1.y = accf[i][2].y;
        v1.z = accf[i][3].x; v1.w = accf[i][3].y;
        if (z < 7) {
            uint2 h0 = f4_to_h4(v0);
            uint2 h1 = f4_to_h4(v1);
            uint4 hv = make_uint4(h0.x, h0.y, h1.x, h1.y);
            *reinterpret_cast<uint4*>(
                g_vh + (size_t)m * (7 * CTD) + (size_t)z * CTD + n) = hv;
        } else {
            float4 b0 = *reinterpret_cast<const float4*>(bias + n);
            float4 b1 = *reinterpret_cast<const float4*>(bias + n + 4);
            v0.x += b0.x; v0.y += b0.y; v0.z += b0.z; v0.w += b0.w;
            v1.x += b1.x; v1.y += b1.y; v1.z += b1.z; v1.w += b1.w;
            float* dst = g_vin + (size_t)m * CTD + n;
            *reinterpret_cast<float4*>(dst)     = v0;
            *reinterpret_cast<float4*>(dst + 4) = v1;
        }
    }
}

// ---------------- 2b) selector-variant GEMM — gemm2 (experiment) -----------
// A stored RAW (k-major halves, no duplication); inner loop reads 1 LDS.128
// per k and relies on ptxas folding __low2half2/__high2half2 into HFMA2
// half-lane selectors (.H0_H0/.H1_H1).
template<int NKT>
__global__ void __launch_bounds__(256, 2) gemm_hsel(
    const float* __restrict__ bias,
    const float* __restrict__ teacher)
{
    __shared__ __align__(16) __half As[2][KT][128];   // raw k-major, 16 KB
    __shared__ __align__(16) __half Bs[2][KT][128];   // 16 KB

    int tid = threadIdx.x;
    int m0 = blockIdx.y * 128, n0 = blockIdx.x * 128;

    const __half* A = g_fuse;
    const __half* B = g_woh;
    const int lda = CTD;

    int arow = tid >> 1, acol = (tid & 1) * 16;
    const __half* ag = A + (size_t)(m0 + arow) * lda + acol;
    int brow = tid >> 3, bcol = (tid & 7) * 16;
    const __half* bg = B + (size_t)brow * CTD + n0 + bcol;

    int ty = tid >> 4, tx = tid & 15;

    float2  accf[8][4];
    __half2 acch[8][4];
#pragma unroll
    for (int i = 0; i < 8; i++)
#pragma unroll
        for (int j = 0; j < 4; j++) {
            accf[i][j] = make_float2(0.f, 0.f);
            acch[i][j] = __half2half2(__ushort_as_half(0));
        }

    uint4 pa0, pa1;

    auto store_a = [&](int buf) {
        const __half* h0 = reinterpret_cast<const __half*>(&pa0);
        const __half* h1 = reinterpret_cast<const __half*>(&pa1);
#pragma unroll
        for (int jj = 0; jj < 8; jj++)
            As[buf][acol + jj][arow] = h0[jj];
#pragma unroll
        for (int jj = 0; jj < 8; jj++)
            As[buf][acol + 8 + jj][arow] = h1[jj];
    };

    pa0 = *reinterpret_cast<const uint4*>(ag);
    pa1 = *reinterpret_cast<const uint4*>(ag + 8);
    cp16(&Bs[0][brow][bcol], bg);
    cp16(&Bs[0][brow][bcol + 8], bg + 8);
    asm volatile("cp.async.commit_group;\n" ::: "memory");
    store_a(0);

    for (int kt = 0; kt < NKT; kt++) {
        int buf = kt & 1;
        asm volatile("cp.async.wait_group 0;\n" ::: "memory");
        __syncthreads();

        if (kt + 1 < NKT) {
            pa0 = *reinterpret_cast<const uint4*>(ag + (kt + 1) * KT);
            pa1 = *reinterpret_cast<const uint4*>(ag + (kt + 1) * KT + 8);
            const __half* bn = bg + (size_t)(kt + 1) * KT * CTD;
            cp16(&Bs[buf ^ 1][brow][bcol], bn);
            cp16(&Bs[buf ^ 1][brow][bcol + 8], bn + 8);
            asm volatile("cp.async.commit_group;\n" ::: "memory");
        }

#pragma unroll
        for (int k = 0; k < KT; k++) {
            __half2 ap[4], b2[4];
            *reinterpret_cast<uint4*>(&ap[0]) =
                *reinterpret_cast<const uint4*>(&As[buf][k][ty * 8]);
            *reinterpret_cast<uint4*>(&b2[0]) =
                *reinterpret_cast<const uint4*>(&Bs[buf][k][tx * 8]);
#pragma unroll
            for (int i2 = 0; i2 < 4; i2++) {
                __half2 alo = __low2half2(ap[i2]);    // {lo,lo} -> H0_H0
                __half2 ahi = __high2half2(ap[i2]);   // {hi,hi} -> H1_H1
#pragma unroll
                for (int j = 0; j < 4; j++) {
                    acch[2 * i2][j]     = __hfma2(alo, b2[j], acch[2 * i2][j]);
                    acch[2 * i2 + 1][j] = __hfma2(ahi, b2[j], acch[2 * i2 + 1][j]);
                }
            }
        }

        if (kt + 1 < NKT) store_a(buf ^ 1);

        if ((kt & 7) == 7 || kt == NKT - 1) {
#pragma unroll
            for (int i = 0; i < 8; i++)
#pragma unroll
                for (int j = 0; j < 4; j++) {
                    float2 t = __half22float2(acch[i][j]);
                    accf[i][j].x += t.x;
                    accf[i][j].y += t.y;
                    acch[i][j] = __half2half2(__ushort_as_half(0));
                }
        }
    }

#pragma unroll
    for (int i = 0; i < 8; i++) {
        int m = m0 + ty * 8 + i;
        int n = n0 + tx * 8;
        float4 v0, v1;
        v0.x = accf[i][0].x; v0.y = accf[i][0].y;
        v0.z = accf[i][1].x; v0.w = accf[i][1].y;
        v1.x = accf[i][2].x; v1.y = accf[i][2].y;
        v1.z = accf[i][3].x; v1.w = accf[i][3].y;
        float4 b0 = *reinterpret_cast<const float4*>(bias + n);
        float4 b1 = *reinterpret_cast<const float4*>(bias + n + 4);
        const float* vin = g_vin + (size_t)m * CTD + n;
        float4 i0 = *reinterpret_cast<const float4*>(vin);
        float4 i1 = *reinterpret_cast<const float4*>(vin + 4);
        v0.x += b0.x + i0.x; v0.y += b0.y + i0.y;
        v0.z += b0.z + i0.z; v0.w += b0.w + i0.w;
        v1.x += b1.x + i1.x; v1.y += b1.y + i1.y;
        v1.z += b1.z + i1.z; v1.w += b1.w + i1.w;
        const float* tr = teacher + (size_t)m * CTD + n;
        float4 t0 = *reinterpret_cast<const float4*>(tr);
        float4 t1 = *reinterpret_cast<const float4*>(tr + 4);
        float pd = v0.x*t0.x + v0.y*t0.y + v0.z*t0.z + v0.w*t0.w
                 + v1.x*t1.x + v1.y*t1.y + v1.z*t1.z + v1.w*t1.w;
        float pn = v0.x*v0.x + v0.y*v0.y + v0.z*v0.z + v0.w*v0.w
                 + v1.x*v1.x + v1.y*v1.y + v1.z*v1.z + v1.w*v1.w;
#pragma unroll
        for (int o = 8; o > 0; o >>= 1) {
            pd += __shfl_xor_sync(0xffffffffu, pd, o);
            pn += __shfl_xor_sync(0xffffffffu, pn, o);
        }
        if (tx == 0) {
            float* dst = g_part + ((size_t)blockIdx.x * MTOT + m) * 2;
            dst[0] = pd;
            dst[1] = pn;
        }
    }
}

// ---------------- 3) attention fuse: one warp per (m, head) ----------------
__global__ void __launch_bounds__(256) attn_kernel()
{
    int m = blockIdx.x;
    int h = threadIdx.x >> 5;
    int lane = threadIdx.x & 31;
    const __half* vrow = g_vh + (size_t)m * 7 * CTD + h * HDIM + lane * 4;

    float q[4], kv[6][4];
    {
        uint2 r = *reinterpret_cast<const uint2*>(vrow);
        float2 a = __half22float2(*reinterpret_cast<__half2*>(&r.x));
        float2 b = __half22float2(*reinterpret_cast<__half2*>(&r.y));
        q[0] = a.x * ATT_SCALE; q[1] = a.y * ATT_SCALE;
        q[2] = b.x * ATT_SCALE; q[3] = b.y * ATT_SCALE;
    }
#pragma unroll
    for (int l = 0; l < 6; l++) {
        uint2 r = *reinterpret_cast<const uint2*>(vrow + (size_t)(l + 1) * CTD);
        float2 a = __half22float2(*reinterpret_cast<__half2*>(&r.x));
        float2 b = __half22float2(*reinterpret_cast<__half2*>(&r.y));
        kv[l][0] = a.x; kv[l][1] = a.y; kv[l][2] = b.x; kv[l][3] = b.y;
    }

    float logit[6];
#pragma unroll
    for (int l = 0; l < 6; l++) {
        float p = q[0] * kv[l][0] + q[1] * kv[l][1]
                + q[2] * kv[l][2] + q[3] * kv[l][3];
        logit[l] = warp_sum(p);
    }

    float mx = -1e30f;
#pragma unroll
    for (int l = 0; l < 6; l++) mx = fmaxf(mx, logit[l]);
    float e[6], sum = 0.f;
#pragma unroll
    for (int l = 0; l < 6; l++) { e[l] = expf(logit[l] - mx); sum += e[l]; }
    float inv = 1.0f / sum;

    float f[4] = {0.f, 0.f, 0.f, 0.f};
#pragma unroll
    for (int l = 0; l < 6; l++) {
        float w = e[l] * inv;
#pragma unroll
        for (int d = 0; d < 4; d++) f[d] += w * kv[l][d];
    }

    __half2 lo = __floats2half2_rn(f[0], f[1]);
    __half2 hi = __floats2half2_rn(f[2], f[3]);
    uint2 outv;
    outv.x = *reinterpret_cast<uint32_t*>(&lo);
    outv.y = *reinterpret_cast<uint32_t*>(&hi);
    *reinterpret_cast<uint2*>(
        g_fuse + (size_t)m * CTD + h * HDIM + lane * 4) = outv;
}

// ---------------- 4) final: combine strips, cosine, deterministic mean ------
__global__ void __launch_bounds__(512) final_kernel(float* __restrict__ out)
{
    __shared__ float sh[512];
    int t = threadIdx.x;
    float s = 0.f;
    for (int m = t; m < MTOT; m += 512) {
        float dot = 0.f, n1 = 0.f;
#pragma unroll
        for (int st = 0; st < 8; st++) {
            const float* p = g_part + ((size_t)st * MTOT + m) * 2;
            dot += p[0];
            n1  += p[1];
        }
        float na = fmaxf(sqrtf(n1), COS_EPSF);
        float nb = fmaxf(sqrtf(g_n2[m]), COS_EPSF);
        s += dot / (na * nb);
    }
    sh[t] = s;
    __syncthreads();
    for (int o = 256; o > 0; o >>= 1) {
        if (t < o) sh[t] += sh[t + o];
        __syncthreads();
    }
    if (t == 0) out[0] = 1.0f - sh[0] / (float)MTOT;
}

// ---------------- launch ----------------
extern "C" void kernel_launch(void* const* d_in, const int* in_sizes, int n_in,
                              void* d_out, int out_size)
{
    const float* features = (const float*)d_in[0];
    const float* teacher  = (const float*)d_in[1];
    const float* ln_scale = (const float*)d_in[2];
    const float* ln_bias  = (const float*)d_in[3];
    const float* w_norm   = (const float*)d_in[4];
    const float* w_in     = (const float*)d_in[5];
    const float* b_in     = (const float*)d_in[6];
    const float* w_out    = (const float*)d_in[7];
    const float* b_out    = (const float*)d_in[8];
    float* out = (float*)d_out;

    prep_kernel<<<PREP_BLOCKS, 256>>>(
        features, ln_scale, ln_bias, w_norm, w_in, w_out, teacher);
    gemm_h5<DIM / KT><<<dim3(CTD / 128, MTOT / 128, 8), 256>>>(b_in);
    attn_kernel<<<MTOT, 256>>>();
    gemm_hsel<CTD / KT><<<dim3(CTD / 128, MTOT / 128), 256>>>(b_out, teacher);
    final_kernel<<<1, 512>>>(out);
}

// round 16
// speedup vs baseline: 1.0408x; 1.0284x over previous
#include <cuda_runtime.h>
#include <cuda_fp16.h>
#include <math.h>
#include <stdint.h>

// ---------------- problem constants ----------------
#define BT      8
#define SEQ     576
#define MTOT    (BT * SEQ)        // 4608
#define NLF     25
#define DIM     2048              // D
#define CTD     1024              // CT
#define HEADS   8
#define HDIM    128
#define ATT_SCALE 0.03125f
#define LN_EPSF   1e-5f
#define COS_EPSF  1e-8f

// ---------------- device scratch ----------------
__device__ __half g_xn[(size_t)8 * MTOT * DIM];   // slots 0..6 LN'd layers, slot 7 raw layer 24
__device__ __half g_wh[(size_t)8 * DIM * CTD];    // slots 0..6 w_norm, slot 7 w_in (fp16)
__device__ __half g_woh[(size_t)CTD * CTD];       // w_out fp16
__device__ __half g_vh[(size_t)MTOT * 7 * CTD];   // vout slots 0..6, fp16
__device__ float  g_vin[(size_t)MTOT * CTD];      // vin fp32
__device__ __half g_fuse[(size_t)MTOT * CTD];
__device__ float  g_part[(size_t)8 * MTOT * 2];   // per-strip (dot, n1) partials
__device__ float  g_n2[MTOT];                     // teacher squared norms

// ---------------- helpers ----------------
__device__ __forceinline__ float warp_sum(float v) {
#pragma unroll
    for (int o = 16; o > 0; o >>= 1) v += __shfl_xor_sync(0xffffffffu, v, o);
    return v;
}
__device__ __forceinline__ void cp16(void* dst, const void* src) {
    uint32_t d = (uint32_t)__cvta_generic_to_shared(dst);
    asm volatile("cp.async.cg.shared.global [%0], [%1], 16;\n" :: "r"(d), "l"(src));
}
__device__ __forceinline__ uint2 f4_to_h4(float4 v) {
    __half2 lo = __floats2half2_rn(v.x, v.y);
    __half2 hi = __floats2half2_rn(v.z, v.w);
    uint2 r;
    r.x = *reinterpret_cast<uint32_t*>(&lo);
    r.y = *reinterpret_cast<uint32_t*>(&hi);
    return r;
}

// ---------------- 1) fused prep: LN, weight conversion, teacher norms -------
#define WN4 ((size_t)7 * DIM * CTD / 4)
#define WI4 ((size_t)DIM * CTD / 4)
#define WO4 ((size_t)CTD * CTD / 4)
#define LN_BLOCKS (MTOT * 7)
#define CW_TOTAL  (WN4 + WI4 + WO4)
#define CW_BLOCKS ((unsigned)((CW_TOTAL + 255) / 256))
#define PREP_BLOCKS (LN_BLOCKS + CW_BLOCKS + MTOT)

__global__ void __launch_bounds__(256) prep_kernel(
    const float* __restrict__ features,
    const float* __restrict__ ln_scale,
    const float* __restrict__ ln_bias,
    const float* __restrict__ wn,
    const float* __restrict__ wi,
    const float* __restrict__ wo,
    const float* __restrict__ teacher)
{
    if (blockIdx.x >= LN_BLOCKS + CW_BLOCKS) {
        int m = blockIdx.x - (LN_BLOCKS + CW_BLOCKS);
        int t = threadIdx.x;
        float4 y = reinterpret_cast<const float4*>(teacher + (size_t)m * CTD)[t];
        float n2 = y.x*y.x + y.y*y.y + y.z*y.z + y.w*y.w;
        __shared__ float s2[8];
        float w2 = warp_sum(n2);
        int w = t >> 5, lane = t & 31;
        if (lane == 0) s2[w] = w2;
        __syncthreads();
        if (t == 0) {
            float tot = 0.f;
#pragma unroll
            for (int i = 0; i < 8; i++) tot += s2[i];
            g_n2[m] = tot;
        }
        return;
    }
    if (blockIdx.x >= LN_BLOCKS) {
        size_t i = (size_t)(blockIdx.x - LN_BLOCKS) * 256 + threadIdx.x;
        if (i < WN4) {
            reinterpret_cast<uint2*>(g_wh)[i] =
                f4_to_h4(reinterpret_cast<const float4*>(wn)[i]);
        } else if (i < WN4 + WI4) {
            size_t j = i - WN4;
            reinterpret_cast<uint2*>(g_wh + (size_t)7 * DIM * CTD)[j] =
                f4_to_h4(reinterpret_cast<const float4*>(wi)[j]);
        } else if (i < WN4 + WI4 + WO4) {
            size_t j = i - WN4 - WI4;
            reinterpret_cast<uint2*>(g_woh)[j] =
                f4_to_h4(reinterpret_cast<const float4*>(wo)[j]);
        }
        return;
    }

    int l = blockIdx.x % 7;
    int m = blockIdx.x / 7;
    int layer = 24 - 4 * l;
    const float4* x = reinterpret_cast<const float4*>(
        features + ((size_t)m * NLF + layer) * DIM);
    int t = threadIdx.x;

    float4 a = x[t];
    float4 b = x[t + 256];
    uint2* o = reinterpret_cast<uint2*>(g_xn + ((size_t)l * MTOT + m) * DIM);

    if (l == 0) {
        uint2* o7 = reinterpret_cast<uint2*>(g_xn + ((size_t)7 * MTOT + m) * DIM);
        o7[t] = f4_to_h4(a);
        o7[t + 256] = f4_to_h4(b);
    }

    float s  = a.x + a.y + a.z + a.w + b.x + b.y + b.z + b.w;
    float ss = a.x*a.x + a.y*a.y + a.z*a.z + a.w*a.w
             + b.x*b.x + b.y*b.y + b.z*b.z + b.w*b.w;

    __shared__ float shs[8], shss[8];
    float ws  = warp_sum(s);
    float wss = warp_sum(ss);
    int w = t >> 5, lane = t & 31;
    if (lane == 0) { shs[w] = ws; shss[w] = wss; }
    __syncthreads();
    float tot = 0.f, tot2 = 0.f;
#pragma unroll
    for (int i = 0; i < 8; i++) { tot += shs[i]; tot2 += shss[i]; }

    float mu  = tot * (1.0f / DIM);
    float var = tot2 * (1.0f / DIM) - mu * mu;
    float rs  = rsqrtf(var + LN_EPSF);

    const float4* sc = reinterpret_cast<const float4*>(ln_scale + (size_t)l * DIM);
    const float4* bi = reinterpret_cast<const float4*>(ln_bias  + (size_t)l * DIM);
    float4 s0 = sc[t],       b0 = bi[t];
    float4 s1 = sc[t + 256], b1 = bi[t + 256];
    float4 o0, o1;
    o0.x = (a.x - mu) * rs * s0.x + b0.x;
    o0.y = (a.y - mu) * rs * s0.y + b0.y;
    o0.z = (a.z - mu) * rs * s0.z + b0.z;
    o0.w = (a.w - mu) * rs * s0.w + b0.w;
    o1.x = (b.x - mu) * rs * s1.x + b1.x;
    o1.y = (b.y - mu) * rs * s1.y + b1.y;
    o1.z = (b.z - mu) * rs * s1.z + b1.z;
    o1.w = (b.w - mu) * rs * s1.w + b1.w;
    o[t] = f4_to_h4(o0);
    o[t + 256] = f4_to_h4(o1);
}

// ---------------- 2) selector HFMA2 GEMM: 128x128x32, 256 thr, 8Mx8N --------
// A stored RAW k-major in smem (1 LDS.128 per k); HFMA2 half-lane selectors
// (.H0_H0/.H1_H1) give the per-row broadcast for free.
// half2 accumulators flushed to fp32 regs every 8 K-tiles (K=256 window).
// MODE 0: g_xn[z] @ g_wh[z] -> z<7: g_vh slot z (fp16); z==7: g_vin + b_in
// MODE 1: g_fuse @ g_woh + vin + b_out; fused cosine partials -> g_part
#define KT 32
template<int NKT, int MODE>
__global__ void __launch_bounds__(256, 2) gemm_hsel(
    const float* __restrict__ bias,
    const float* __restrict__ teacher)
{
    __shared__ __align__(16) __half As[2][KT][128];   // raw k-major, 16 KB
    __shared__ __align__(16) __half Bs[2][KT][128];   // 16 KB

    int tid = threadIdx.x;
    int m0 = blockIdx.y * 128, n0 = blockIdx.x * 128;
    int z = (MODE == 0) ? blockIdx.z : 0;

    const __half* A;
    const __half* B;
    if (MODE == 0) {
        A = g_xn + (size_t)z * MTOT * DIM;
        B = g_wh + (size_t)z * DIM * CTD;
    } else {
        A = g_fuse;
        B = g_woh;
    }
    const int lda = (MODE == 0) ? DIM : CTD;

    int arow = tid >> 1, acol = (tid & 1) * 16;
    const __half* ag = A + (size_t)(m0 + arow) * lda + acol;
    int brow = tid >> 3, bcol = (tid & 7) * 16;
    const __half* bg = B + (size_t)brow * CTD + n0 + bcol;

    int ty = tid >> 4, tx = tid & 15;

    float2  accf[8][4];
    __half2 acch[8][4];
#pragma unroll
    for (int i = 0; i < 8; i++)
#pragma unroll
        for (int j = 0; j < 4; j++) {
            accf[i][j] = make_float2(0.f, 0.f);
            acch[i][j] = __half2half2(__ushort_as_half(0));
        }

    uint4 pa0, pa1;

    auto store_a = [&](int buf) {
        const __half* h0 = reinterpret_cast<const __half*>(&pa0);
        const __half* h1 = reinterpret_cast<const __half*>(&pa1);
#pragma unroll
        for (int jj = 0; jj < 8; jj++)
            As[buf][acol + jj][arow] = h0[jj];
#pragma unroll
        for (int jj = 0; jj < 8; jj++)
            As[buf][acol + 8 + jj][arow] = h1[jj];
    };

    pa0 = *reinterpret_cast<const uint4*>(ag);
    pa1 = *reinterpret_cast<const uint4*>(ag + 8);
    cp16(&Bs[0][brow][bcol], bg);
    cp16(&Bs[0][brow][bcol + 8], bg + 8);
    asm volatile("cp.async.commit_group;\n" ::: "memory");
    store_a(0);

    for (int kt = 0; kt < NKT; kt++) {
        int buf = kt & 1;
        asm volatile("cp.async.wait_group 0;\n" ::: "memory");
        __syncthreads();

        if (kt + 1 < NKT) {
            pa0 = *reinterpret_cast<const uint4*>(ag + (kt + 1) * KT);
            pa1 = *reinterpret_cast<const uint4*>(ag + (kt + 1) * KT + 8);
            const __half* bn = bg + (size_t)(kt + 1) * KT * CTD;
            cp16(&Bs[buf ^ 1][brow][bcol], bn);
            cp16(&Bs[buf ^ 1][brow][bcol + 8], bn + 8);
            asm volatile("cp.async.commit_group;\n" ::: "memory");
        }

#pragma unroll
        for (int k = 0; k < KT; k++) {
            __half2 ap[4], b2[4];
            *reinterpret_cast<uint4*>(&ap[0]) =
                *reinterpret_cast<const uint4*>(&As[buf][k][ty * 8]);
            *reinterpret_cast<uint4*>(&b2[0]) =
                *reinterpret_cast<const uint4*>(&Bs[buf][k][tx * 8]);
#pragma unroll
            for (int i2 = 0; i2 < 4; i2++) {
                __half2 alo = __low2half2(ap[i2]);    // -> .H0_H0 selector
                __half2 ahi = __high2half2(ap[i2]);   // -> .H1_H1 selector
#pragma unroll
                for (int j = 0; j < 4; j++) {
                    acch[2 * i2][j]     = __hfma2(alo, b2[j], acch[2 * i2][j]);
                    acch[2 * i2 + 1][j] = __hfma2(ahi, b2[j], acch[2 * i2 + 1][j]);
                }
            }
        }

        if (kt + 1 < NKT) store_a(buf ^ 1);

        if ((kt & 7) == 7 || kt == NKT - 1) {
#pragma unroll
            for (int i = 0; i < 8; i++)
#pragma unroll
                for (int j = 0; j < 4; j++) {
                    float2 t = __half22float2(acch[i][j]);
                    accf[i][j].x += t.x;
                    accf[i][j].y += t.y;
                    acch[i][j] = __half2half2(__ushort_as_half(0));
                }
        }
    }

    // ---- epilogue: 8 rows x 8 cols per thread ----
#pragma unroll
    for (int i = 0; i < 8; i++) {
        int m = m0 + ty * 8 + i;
        int n = n0 + tx * 8;
        float4 v0, v1;
        v0.x = accf[i][0].x; v0.y = accf[i][0].y;
        v0.z = accf[i][1].x; v0.w = accf[i][1].y;
        v1.x = accf[i][2].x; v1.y = accf[i][2].y;
        v1.z = accf[i][3].x; v1.w = accf[i][3].y;
        if (MODE == 0) {
            if (z < 7) {
                uint2 h0 = f4_to_h4(v0);
                uint2 h1 = f4_to_h4(v1);
                uint4 hv = make_uint4(h0.x, h0.y, h1.x, h1.y);
                *reinterpret_cast<uint4*>(
                    g_vh + (size_t)m * (7 * CTD) + (size_t)z * CTD + n) = hv;
            } else {
                float4 b0 = *reinterpret_cast<const float4*>(bias + n);
                float4 b1 = *reinterpret_cast<const float4*>(bias + n + 4);
                v0.x += b0.x; v0.y += b0.y; v0.z += b0.z; v0.w += b0.w;
                v1.x += b1.x; v1.y += b1.y; v1.z += b1.z; v1.w += b1.w;
                float* dst = g_vin + (size_t)m * CTD + n;
                *reinterpret_cast<float4*>(dst)     = v0;
                *reinterpret_cast<float4*>(dst + 4) = v1;
            }
        } else {
            float4 b0 = *reinterpret_cast<const float4*>(bias + n);
            float4 b1 = *reinterpret_cast<const float4*>(bias + n + 4);
            const float* vin = g_vin + (size_t)m * CTD + n;
            float4 i0 = *reinterpret_cast<const float4*>(vin);
            float4 i1 = *reinterpret_cast<const float4*>(vin + 4);
            v0.x += b0.x + i0.x; v0.y += b0.y + i0.y;
            v0.z += b0.z + i0.z; v0.w += b0.w + i0.w;
            v1.x += b1.x + i1.x; v1.y += b1.y + i1.y;
            v1.z += b1.z + i1.z; v1.w += b1.w + i1.w;
            const float* tr = teacher + (size_t)m * CTD + n;
            float4 t0 = *reinterpret_cast<const float4*>(tr);
            float4 t1 = *reinterpret_cast<const float4*>(tr + 4);
            float pd = v0.x*t0.x + v0.y*t0.y + v0.z*t0.z + v0.w*t0.w
                     + v1.x*t1.x + v1.y*t1.y + v1.z*t1.z + v1.w*t1.w;
            float pn = v0.x*v0.x + v0.y*v0.y + v0.z*v0.z + v0.w*v0.w
                     + v1.x*v1.x + v1.y*v1.y + v1.z*v1.z + v1.w*v1.w;
#pragma unroll
            for (int o = 8; o > 0; o >>= 1) {
                pd += __shfl_xor_sync(0xffffffffu, pd, o);
                pn += __shfl_xor_sync(0xffffffffu, pn, o);
            }
            if (tx == 0) {
                float* dst = g_part + ((size_t)blockIdx.x * MTOT + m) * 2;
                dst[0] = pd;
                dst[1] = pn;
            }
        }
    }
}

// ---------------- 3) attention fuse: one warp per (m, head) ----------------
__global__ void __launch_bounds__(256) attn_kernel()
{
    int m = blockIdx.x;
    int h = threadIdx.x >> 5;
    int lane = threadIdx.x & 31;
    const __half* vrow = g_vh + (size_t)m * 7 * CTD + h * HDIM + lane * 4;

    float q[4], kv[6][4];
    {
        uint2 r = *reinterpret_cast<const uint2*>(vrow);
        float2 a = __half22float2(*reinterpret_cast<__half2*>(&r.x));
        float2 b = __half22float2(*reinterpret_cast<__half2*>(&r.y));
        q[0] = a.x * ATT_SCALE; q[1] = a.y * ATT_SCALE;
        q[2] = b.x * ATT_SCALE; q[3] = b.y * ATT_SCALE;
    }
#pragma unroll
    for (int l = 0; l < 6; l++) {
        uint2 r = *reinterpret_cast<const uint2*>(vrow + (size_t)(l + 1) * CTD);
        float2 a = __half22float2(*reinterpret_cast<__half2*>(&r.x));
        float2 b = __half22float2(*reinterpret_cast<__half2*>(&r.y));
        kv[l][0] = a.x; kv[l][1] = a.y; kv[l][2] = b.x; kv[l][3] = b.y;
    }

    float logit[6];
#pragma unroll
    for (int l = 0; l < 6; l++) {
        float p = q[0] * kv[l][0] + q[1] * kv[l][1]
                + q[2] * kv[l][2] + q[3] * kv[l][3];
        logit[l] = warp_sum(p);
    }

    float mx = -1e30f;
#pragma unroll
    for (int l = 0; l < 6; l++) mx = fmaxf(mx, logit[l]);
    float e[6], sum = 0.f;
#pragma unroll
    for (int l = 0; l < 6; l++) { e[l] = expf(logit[l] - mx); sum += e[l]; }
    float inv = 1.0f / sum;

    float f[4] = {0.f, 0.f, 0.f, 0.f};
#pragma unroll
    for (int l = 0; l < 6; l++) {
        float w = e[l] * inv;
#pragma unroll
        for (int d = 0; d < 4; d++) f[d] += w * kv[l][d];
    }

    __half2 lo = __floats2half2_rn(f[0], f[1]);
    __half2 hi = __floats2half2_rn(f[2], f[3]);
    uint2 outv;
    outv.x = *reinterpret_cast<uint32_t*>(&lo);
    outv.y = *reinterpret_cast<uint32_t*>(&hi);
    *reinterpret_cast<uint2*>(
        g_fuse + (size_t)m * CTD + h * HDIM + lane * 4) = outv;
}

// ---------------- 4) final: combine strips, cosine, deterministic mean ------
__global__ void __launch_bounds__(512) final_kernel(float* __restrict__ out)
{
    __shared__ float sh[512];
    int t = threadIdx.x;
    float s = 0.f;
    for (int m = t; m < MTOT; m += 512) {
        float dot = 0.f, n1 = 0.f;
#pragma unroll
        for (int st = 0; st < 8; st++) {
            const float* p = g_part + ((size_t)st * MTOT + m) * 2;
            dot += p[0];
            n1  += p[1];
        }
        float na = fmaxf(sqrtf(n1), COS_EPSF);
        float nb = fmaxf(sqrtf(g_n2[m]), COS_EPSF);
        s += dot / (na * nb);
    }
    sh[t] = s;
    __syncthreads();
    for (int o = 256; o > 0; o >>= 1) {
        if (t < o) sh[t] += sh[t + o];
        __syncthreads();
    }
    if (t == 0) out[0] = 1.0f - sh[0] / (float)MTOT;
}

// ---------------- launch ----------------
extern "C" void kernel_launch(void* const* d_in, const int* in_sizes, int n_in,
                              void* d_out, int out_size)
{
    const float* features = (const float*)d_in[0];
    const float* teacher  = (const float*)d_in[1];
    const float* ln_scale = (const float*)d_in[2];
    const float* ln_bias  = (const float*)d_in[3];
    const float* w_norm   = (const float*)d_in[4];
    const float* w_in     = (const float*)d_in[5];
    const float* b_in     = (const float*)d_in[6];
    const float* w_out    = (const float*)d_in[7];
    const float* b_out    = (const float*)d_in[8];
    float* out = (float*)d_out;

    prep_kernel<<<PREP_BLOCKS, 256>>>(
        features, ln_scale, ln_bias, w_norm, w_in, w_out, teacher);
    gemm_hsel<DIM / KT, 0><<<dim3(CTD / 128, MTOT / 128, 8), 256>>>(b_in, nullptr);
    attn_kernel<<<MTOT, 256>>>();
    gemm_hsel<CTD / KT, 1><<<dim3(CTD / 128, MTOT / 128), 256>>>(b_out, teacher);
    final_kernel<<<1, 512>>>(out);
}

// round 17
// speedup vs baseline: 1.1101x; 1.0666x over previous
#include <cuda_runtime.h>
#include <cuda_fp16.h>
#include <math.h>
#include <stdint.h>

// ---------------- problem constants ----------------
#define BT      8
#define SEQ     576
#define MTOT    (BT * SEQ)        // 4608
#define NLF     25
#define DIM     2048              // D
#define CTD     1024              // CT
#define HEADS   8
#define HDIM    128
#define ATT_SCALE 0.03125f
#define LN_EPSF   1e-5f
#define COS_EPSF  1e-8f

// ---------------- device scratch ----------------
__device__ __half g_xn[(size_t)8 * MTOT * DIM];   // slots 0..6 LN'd layers, slot 7 raw layer 24
__device__ __half g_wh[(size_t)8 * DIM * CTD];    // slots 0..6 w_norm, slot 7 w_in (fp16)
__device__ __half g_woh[(size_t)CTD * CTD];       // w_out fp16
__device__ __half g_vh[(size_t)MTOT * 7 * CTD];   // vout slots 0..6, fp16
__device__ float  g_vin[(size_t)MTOT * CTD];      // vin fp32
__device__ __half g_fuse[(size_t)MTOT * CTD];
__device__ float  g_part[(size_t)8 * MTOT * 2];   // per-strip (dot, n1) partials
__device__ float  g_n2[MTOT];                     // teacher squared norms

// ---------------- helpers ----------------
__device__ __forceinline__ float warp_sum(float v) {
#pragma unroll
    for (int o = 16; o > 0; o >>= 1) v += __shfl_xor_sync(0xffffffffu, v, o);
    return v;
}
__device__ __forceinline__ void cp16(void* dst, const void* src) {
    uint32_t d = (uint32_t)__cvta_generic_to_shared(dst);
    asm volatile("cp.async.cg.shared.global [%0], [%1], 16;\n" :: "r"(d), "l"(src));
}
__device__ __forceinline__ uint2 f4_to_h4(float4 v) {
    __half2 lo = __floats2half2_rn(v.x, v.y);
    __half2 hi = __floats2half2_rn(v.z, v.w);
    uint2 r;
    r.x = *reinterpret_cast<uint32_t*>(&lo);
    r.y = *reinterpret_cast<uint32_t*>(&hi);
    return r;
}

// ---------------- 1) fused prep: LN, weight conversion, teacher norms -------
#define WN4 ((size_t)7 * DIM * CTD / 4)
#define WI4 ((size_t)DIM * CTD / 4)
#define WO4 ((size_t)CTD * CTD / 4)
#define LN_BLOCKS (MTOT * 7)
#define CW_TOTAL  (WN4 + WI4 + WO4)
#define CW_BLOCKS ((unsigned)((CW_TOTAL + 255) / 256))
#define PREP_BLOCKS (LN_BLOCKS + CW_BLOCKS + MTOT)

__global__ void __launch_bounds__(256) prep_kernel(
    const float* __restrict__ features,
    const float* __restrict__ ln_scale,
    const float* __restrict__ ln_bias,
    const float* __restrict__ wn,
    const float* __restrict__ wi,
    const float* __restrict__ wo,
    const float* __restrict__ teacher)
{
    if (blockIdx.x >= LN_BLOCKS + CW_BLOCKS) {
        int m = blockIdx.x - (LN_BLOCKS + CW_BLOCKS);
        int t = threadIdx.x;
        float4 y = reinterpret_cast<const float4*>(teacher + (size_t)m * CTD)[t];
        float n2 = y.x*y.x + y.y*y.y + y.z*y.z + y.w*y.w;
        __shared__ float s2[8];
        float w2 = warp_sum(n2);
        int w = t >> 5, lane = t & 31;
        if (lane == 0) s2[w] = w2;
        __syncthreads();
        if (t == 0) {
            float tot = 0.f;
#pragma unroll
            for (int i = 0; i < 8; i++) tot += s2[i];
            g_n2[m] = tot;
        }
        return;
    }
    if (blockIdx.x >= LN_BLOCKS) {
        size_t i = (size_t)(blockIdx.x - LN_BLOCKS) * 256 + threadIdx.x;
        if (i < WN4) {
            reinterpret_cast<uint2*>(g_wh)[i] =
                f4_to_h4(reinterpret_cast<const float4*>(wn)[i]);
        } else if (i < WN4 + WI4) {
            size_t j = i - WN4;
            reinterpret_cast<uint2*>(g_wh + (size_t)7 * DIM * CTD)[j] =
                f4_to_h4(reinterpret_cast<const float4*>(wi)[j]);
        } else if (i < WN4 + WI4 + WO4) {
            size_t j = i - WN4 - WI4;
            reinterpret_cast<uint2*>(g_woh)[j] =
                f4_to_h4(reinterpret_cast<const float4*>(wo)[j]);
        }
        return;
    }

    int l = blockIdx.x % 7;
    int m = blockIdx.x / 7;
    int layer = 24 - 4 * l;
    const float4* x = reinterpret_cast<const float4*>(
        features + ((size_t)m * NLF + layer) * DIM);
    int t = threadIdx.x;

    float4 a = x[t];
    float4 b = x[t + 256];
    uint2* o = reinterpret_cast<uint2*>(g_xn + ((size_t)l * MTOT + m) * DIM);

    if (l == 0) {
        uint2* o7 = reinterpret_cast<uint2*>(g_xn + ((size_t)7 * MTOT + m) * DIM);
        o7[t] = f4_to_h4(a);
        o7[t + 256] = f4_to_h4(b);
    }

    float s  = a.x + a.y + a.z + a.w + b.x + b.y + b.z + b.w;
    float ss = a.x*a.x + a.y*a.y + a.z*a.z + a.w*a.w
             + b.x*b.x + b.y*b.y + b.z*b.z + b.w*b.w;

    __shared__ float shs[8], shss[8];
    float ws  = warp_sum(s);
    float wss = warp_sum(ss);
    int w = t >> 5, lane = t & 31;
    if (lane == 0) { shs[w] = ws; shss[w] = wss; }
    __syncthreads();
    float tot = 0.f, tot2 = 0.f;
#pragma unroll
    for (int i = 0; i < 8; i++) { tot += shs[i]; tot2 += shss[i]; }

    float mu  = tot * (1.0f / DIM);
    float var = tot2 * (1.0f / DIM) - mu * mu;
    float rs  = rsqrtf(var + LN_EPSF);

    const float4* sc = reinterpret_cast<const float4*>(ln_scale + (size_t)l * DIM);
    const float4* bi = reinterpret_cast<const float4*>(ln_bias  + (size_t)l * DIM);
    float4 s0 = sc[t],       b0 = bi[t];
    float4 s1 = sc[t + 256], b1 = bi[t + 256];
    float4 o0, o1;
    o0.x = (a.x - mu) * rs * s0.x + b0.x;
    o0.y = (a.y - mu) * rs * s0.y + b0.y;
    o0.z = (a.z - mu) * rs * s0.z + b0.z;
    o0.w = (a.w - mu) * rs * s0.w + b0.w;
    o1.x = (b.x - mu) * rs * s1.x + b1.x;
    o1.y = (b.y - mu) * rs * s1.y + b1.y;
    o1.z = (b.z - mu) * rs * s1.z + b1.z;
    o1.w = (b.w - mu) * rs * s1.w + b1.w;
    o[t] = f4_to_h4(o0);
    o[t + 256] = f4_to_h4(o1);
}

// ---------------- 2) selector HFMA2 GEMM: 128x128x32, 256 thr, 8Mx8N --------
// A stored RAW k-major in smem (1 LDS.128 per k); HFMA2 half-lane selectors.
// FULL-K fp16 accumulation (no fp32 flush) -> ~80 regs -> 3 CTAs/SM.
// MODE 0: g_xn[z] @ g_wh[z] -> z<7: g_vh slot z (fp16); z==7: g_vin + b_in
// MODE 1: g_fuse @ g_woh + vin + b_out; fused cosine partials -> g_part
#define KT 32
template<int NKT, int MODE>
__global__ void __launch_bounds__(256, 3) gemm_hsel(
    const float* __restrict__ bias,
    const float* __restrict__ teacher)
{
    __shared__ __align__(16) __half As[2][KT][128];   // raw k-major, 16 KB
    __shared__ __align__(16) __half Bs[2][KT][128];   // 16 KB

    int tid = threadIdx.x;
    int m0 = blockIdx.y * 128, n0 = blockIdx.x * 128;
    int z = (MODE == 0) ? blockIdx.z : 0;

    const __half* A;
    const __half* B;
    if (MODE == 0) {
        A = g_xn + (size_t)z * MTOT * DIM;
        B = g_wh + (size_t)z * DIM * CTD;
    } else {
        A = g_fuse;
        B = g_woh;
    }
    const int lda = (MODE == 0) ? DIM : CTD;

    int arow = tid >> 1, acol = (tid & 1) * 16;
    const __half* ag = A + (size_t)(m0 + arow) * lda + acol;
    int brow = tid >> 3, bcol = (tid & 7) * 16;
    const __half* bg = B + (size_t)brow * CTD + n0 + bcol;

    int ty = tid >> 4, tx = tid & 15;

    __half2 acch[8][4];
#pragma unroll
    for (int i = 0; i < 8; i++)
#pragma unroll
        for (int j = 0; j < 4; j++)
            acch[i][j] = __half2half2(__ushort_as_half(0));

    uint4 pa0, pa1;

    auto store_a = [&](int buf) {
        const __half* h0 = reinterpret_cast<const __half*>(&pa0);
        const __half* h1 = reinterpret_cast<const __half*>(&pa1);
#pragma unroll
        for (int jj = 0; jj < 8; jj++)
            As[buf][acol + jj][arow] = h0[jj];
#pragma unroll
        for (int jj = 0; jj < 8; jj++)
            As[buf][acol + 8 + jj][arow] = h1[jj];
    };

    pa0 = *reinterpret_cast<const uint4*>(ag);
    pa1 = *reinterpret_cast<const uint4*>(ag + 8);
    cp16(&Bs[0][brow][bcol], bg);
    cp16(&Bs[0][brow][bcol + 8], bg + 8);
    asm volatile("cp.async.commit_group;\n" ::: "memory");
    store_a(0);

    for (int kt = 0; kt < NKT; kt++) {
        int buf = kt & 1;
        asm volatile("cp.async.wait_group 0;\n" ::: "memory");
        __syncthreads();

        if (kt + 1 < NKT) {
            pa0 = *reinterpret_cast<const uint4*>(ag + (kt + 1) * KT);
            pa1 = *reinterpret_cast<const uint4*>(ag + (kt + 1) * KT + 8);
            const __half* bn = bg + (size_t)(kt + 1) * KT * CTD;
            cp16(&Bs[buf ^ 1][brow][bcol], bn);
            cp16(&Bs[buf ^ 1][brow][bcol + 8], bn + 8);
            asm volatile("cp.async.commit_group;\n" ::: "memory");
        }

#pragma unroll
        for (int k = 0; k < KT; k++) {
            __half2 ap[4], b2[4];
            *reinterpret_cast<uint4*>(&ap[0]) =
                *reinterpret_cast<const uint4*>(&As[buf][k][ty * 8]);
            *reinterpret_cast<uint4*>(&b2[0]) =
                *reinterpret_cast<const uint4*>(&Bs[buf][k][tx * 8]);
#pragma unroll
            for (int i2 = 0; i2 < 4; i2++) {
                __half2 alo = __low2half2(ap[i2]);    // -> .H0_H0 selector
                __half2 ahi = __high2half2(ap[i2]);   // -> .H1_H1 selector
#pragma unroll
                for (int j = 0; j < 4; j++) {
                    acch[2 * i2][j]     = __hfma2(alo, b2[j], acch[2 * i2][j]);
                    acch[2 * i2 + 1][j] = __hfma2(ahi, b2[j], acch[2 * i2 + 1][j]);
                }
            }
        }

        if (kt + 1 < NKT) store_a(buf ^ 1);
    }

    // ---- epilogue: 8 rows x 8 cols per thread ----
#pragma unroll
    for (int i = 0; i < 8; i++) {
        int m = m0 + ty * 8 + i;
        int n = n0 + tx * 8;
        float2 c0 = __half22float2(acch[i][0]);
        float2 c1 = __half22float2(acch[i][1]);
        float2 c2 = __half22float2(acch[i][2]);
        float2 c3 = __half22float2(acch[i][3]);
        float4 v0 = make_float4(c0.x, c0.y, c1.x, c1.y);
        float4 v1 = make_float4(c2.x, c2.y, c3.x, c3.y);
        if (MODE == 0) {
            if (z < 7) {
                uint2 h0 = f4_to_h4(v0);
                uint2 h1 = f4_to_h4(v1);
                uint4 hv = make_uint4(h0.x, h0.y, h1.x, h1.y);
                *reinterpret_cast<uint4*>(
                    g_vh + (size_t)m * (7 * CTD) + (size_t)z * CTD + n) = hv;
            } else {
                float4 b0 = *reinterpret_cast<const float4*>(bias + n);
                float4 b1 = *reinterpret_cast<const float4*>(bias + n + 4);
                v0.x += b0.x; v0.y += b0.y; v0.z += b0.z; v0.w += b0.w;
                v1.x += b1.x; v1.y += b1.y; v1.z += b1.z; v1.w += b1.w;
                float* dst = g_vin + (size_t)m * CTD + n;
                *reinterpret_cast<float4*>(dst)     = v0;
                *reinterpret_cast<float4*>(dst + 4) = v1;
            }
        } else {
            float4 b0 = *reinterpret_cast<const float4*>(bias + n);
            float4 b1 = *reinterpret_cast<const float4*>(bias + n + 4);
            const float* vin = g_vin + (size_t)m * CTD + n;
            float4 i0 = *reinterpret_cast<const float4*>(vin);
            float4 i1 = *reinterpret_cast<const float4*>(vin + 4);
            v0.x += b0.x + i0.x; v0.y += b0.y + i0.y;
            v0.z += b0.z + i0.z; v0.w += b0.w + i0.w;
            v1.x += b1.x + i1.x; v1.y += b1.y + i1.y;
            v1.z += b1.z + i1.z; v1.w += b1.w + i1.w;
            const float* tr = teacher + (size_t)m * CTD + n;
            float4 t0 = *reinterpret_cast<const float4*>(tr);
            float4 t1 = *reinterpret_cast<const float4*>(tr + 4);
            float pd = v0.x*t0.x + v0.y*t0.y + v0.z*t0.z + v0.w*t0.w
                     + v1.x*t1.x + v1.y*t1.y + v1.z*t1.z + v1.w*t1.w;
            float pn = v0.x*v0.x + v0.y*v0.y + v0.z*v0.z + v0.w*v0.w
                     + v1.x*v1.x + v1.y*v1.y + v1.z*v1.z + v1.w*v1.w;
#pragma unroll
            for (int o = 8; o > 0; o >>= 1) {
                pd += __shfl_xor_sync(0xffffffffu, pd, o);
                pn += __shfl_xor_sync(0xffffffffu, pn, o);
            }
            if (tx == 0) {
                float* dst = g_part + ((size_t)blockIdx.x * MTOT + m) * 2;
                dst[0] = pd;
                dst[1] = pn;
            }
        }
    }
}

// ---------------- 3) attention fuse: one warp per (m, head) ----------------
__global__ void __launch_bounds__(256) attn_kernel()
{
    int m = blockIdx.x;
    int h = threadIdx.x >> 5;
    int lane = threadIdx.x & 31;
    const __half* vrow = g_vh + (size_t)m * 7 * CTD + h * HDIM + lane * 4;

    float q[4], kv[6][4];
    {
        uint2 r = *reinterpret_cast<const uint2*>(vrow);
        float2 a = __half22float2(*reinterpret_cast<__half2*>(&r.x));
        float2 b = __half22float2(*reinterpret_cast<__half2*>(&r.y));
        q[0] = a.x * ATT_SCALE; q[1] = a.y * ATT_SCALE;
        q[2] = b.x * ATT_SCALE; q[3] = b.y * ATT_SCALE;
    }
#pragma unroll
    for (int l = 0; l < 6; l++) {
        uint2 r = *reinterpret_cast<const uint2*>(vrow + (size_t)(l + 1) * CTD);
        float2 a = __half22float2(*reinterpret_cast<__half2*>(&r.x));
        float2 b = __half22float2(*reinterpret_cast<__half2*>(&r.y));
        kv[l][0] = a.x; kv[l][1] = a.y; kv[l][2] = b.x; kv[l][3] = b.y;
    }

    float logit[6];
#pragma unroll
    for (int l = 0; l < 6; l++) {
        float p = q[0] * kv[l][0] + q[1] * kv[l][1]
                + q[2] * kv[l][2] + q[3] * kv[l][3];
        logit[l] = warp_sum(p);
    }

    float mx = -1e30f;
#pragma unroll
    for (int l = 0; l < 6; l++) mx = fmaxf(mx, logit[l]);
    float e[6], sum = 0.f;
#pragma unroll
    for (int l = 0; l < 6; l++) { e[l] = expf(logit[l] - mx); sum += e[l]; }
    float inv = 1.0f / sum;

    float f[4] = {0.f, 0.f, 0.f, 0.f};
#pragma unroll
    for (int l = 0; l < 6; l++) {
        float w = e[l] * inv;
#pragma unroll
        for (int d = 0; d < 4; d++) f[d] += w * kv[l][d];
    }

    __half2 lo = __floats2half2_rn(f[0], f[1]);
    __half2 hi = __floats2half2_rn(f[2], f[3]);
    uint2 outv;
    outv.x = *reinterpret_cast<uint32_t*>(&lo);
    outv.y = *reinterpret_cast<uint32_t*>(&hi);
    *reinterpret_cast<uint2*>(
        g_fuse + (size_t)m * CTD + h * HDIM + lane * 4) = outv;
}

// ---------------- 4) final: combine strips, cosine, deterministic mean ------
__global__ void __launch_bounds__(512) final_kernel(float* __restrict__ out)
{
    __shared__ float sh[512];
    int t = threadIdx.x;
    float s = 0.f;
    for (int m = t; m < MTOT; m += 512) {
        float dot = 0.f, n1 = 0.f;
#pragma unroll
        for (int st = 0; st < 8; st++) {
            const float* p = g_part + ((size_t)st * MTOT + m) * 2;
            dot += p[0];
            n1  += p[1];
        }
        float na = fmaxf(sqrtf(n1), COS_EPSF);
        float nb = fmaxf(sqrtf(g_n2[m]), COS_EPSF);
        s += dot / (na * nb);
    }
    sh[t] = s;
    __syncthreads();
    for (int o = 256; o > 0; o >>= 1) {
        if (t < o) sh[t] += sh[t + o];
        __syncthreads();
    }
    if (t == 0) out[0] = 1.0f - sh[0] / (float)MTOT;
}

// ---------------- launch ----------------
extern "C" void kernel_launch(void* const* d_in, const int* in_sizes, int n_in,
                              void* d_out, int out_size)
{
    const float* features = (const float*)d_in[0];
    const float* teacher  = (const float*)d_in[1];
    const float* ln_scale = (const float*)d_in[2];
    const float* ln_bias  = (const float*)d_in[3];
    const float* w_norm   = (const float*)d_in[4];
    const float* w_in     = (const float*)d_in[5];
    const float* b_in     = (const float*)d_in[6];
    const float* w_out    = (const float*)d_in[7];
    const float* b_out    = (const float*)d_in[8];
    float* out = (float*)d_out;

    prep_kernel<<<PREP_BLOCKS, 256>>>(
        features, ln_scale, ln_bias, w_norm, w_in, w_out, teacher);
    gemm_hsel<DIM / KT, 0><<<dim3(CTD / 128, MTOT / 128, 8), 256>>>(b_in, nullptr);
    attn_kernel<<<MTOT, 256>>>();
    gemm_hsel<CTD / KT, 1><<<dim3(CTD / 128, MTOT / 128), 256>>>(b_out, teacher);
    final_kernel<<<1, 512>>>(out);
}